// round 2
// baseline (speedup 1.0000x reference)
#include <cuda_runtime.h>
#include <math.h>

#define BB 2
#define SS 2048
#define DD 1024
#define HH 16
#define DKK 64

// Scratch (allocation-free rule: __device__ globals)
__device__ float g_tmpq[BB*SS*DD];
__device__ float g_tmpk[BB*SS*DD];
__device__ float g_tmpv[BB*SS*DD];
__device__ float g_qh[BB*SS*DD];   // [B,H,S,DK]
__device__ float g_kh[BB*SS*DD];
__device__ float g_vh[BB*SS*DD];
__device__ float g_attn[BB*SS*DD]; // [B,S,D]
__device__ float g_cos[SS*32];
__device__ float g_sin[SS*32];

// ---------------------------------------------------------------------------
// RoPE tables: cos/sin(p * inv_freq_i), fp64 trig for accuracy at p~2048
// ---------------------------------------------------------------------------
__global__ void rope_table_kernel() {
    int p = blockIdx.x;
    int i = threadIdx.x;  // 0..31
    double inv = exp(-((double)(2 * i) / 64.0) * log(10000.0));
    float angf = (float)((double)p * inv);   // mimic f32 angle of reference
    double a = (double)angf;
    g_cos[p * 32 + i] = (float)cos(a);
    g_sin[p * 32 + i] = (float)sin(a);
}

// ---------------------------------------------------------------------------
// GEMM: C[M,N] = A[M,K] @ W[K,N] + bias,  M=4096, N=K=1024
// 64x64 block tile, BK=16, 256 threads, 4x4 per thread
// ---------------------------------------------------------------------------
__global__ void gemm_bias_kernel(const float* __restrict__ A,
                                 const float* __restrict__ W,
                                 const float* __restrict__ bias,
                                 float* __restrict__ C) {
    __shared__ float As[16][65];  // [k][m], padded
    __shared__ float Ws[16][64];  // [k][n], float4-aligned rows

    int tid = threadIdx.x;
    int tx = tid & 15, ty = tid >> 4;
    int bm = blockIdx.y * 64, bn = blockIdx.x * 64;

    float acc[4][4] = {};

    for (int k0 = 0; k0 < DD; k0 += 16) {
#pragma unroll
        for (int t = 0; t < 4; t++) {
            int idx = tid + t * 256;              // 0..1023
            int m = idx >> 4, kk = idx & 15;      // A tile 64x16
            As[kk][m] = A[(bm + m) * DD + k0 + kk];
            int wk = idx >> 6, wn = idx & 63;     // W tile 16x64
            Ws[wk][wn] = W[(k0 + wk) * DD + bn + wn];
        }
        __syncthreads();
#pragma unroll
        for (int kk = 0; kk < 16; kk++) {
            float a0 = As[kk][ty * 4 + 0];
            float a1 = As[kk][ty * 4 + 1];
            float a2 = As[kk][ty * 4 + 2];
            float a3 = As[kk][ty * 4 + 3];
            float4 w = *(const float4*)&Ws[kk][tx * 4];
            acc[0][0] += a0 * w.x; acc[0][1] += a0 * w.y; acc[0][2] += a0 * w.z; acc[0][3] += a0 * w.w;
            acc[1][0] += a1 * w.x; acc[1][1] += a1 * w.y; acc[1][2] += a1 * w.z; acc[1][3] += a1 * w.w;
            acc[2][0] += a2 * w.x; acc[2][1] += a2 * w.y; acc[2][2] += a2 * w.z; acc[2][3] += a2 * w.w;
            acc[3][0] += a3 * w.x; acc[3][1] += a3 * w.y; acc[3][2] += a3 * w.z; acc[3][3] += a3 * w.w;
        }
        __syncthreads();
    }

#pragma unroll
    for (int i = 0; i < 4; i++) {
        int row = bm + ty * 4 + i;
#pragma unroll
        for (int j = 0; j < 4; j++) {
            int col = bn + tx * 4 + j;
            C[row * DD + col] = acc[i][j] + bias[col];
        }
    }
}

// ---------------------------------------------------------------------------
// RoPE apply + transpose [B,S,D] -> [B,H,S,DK]
// ---------------------------------------------------------------------------
__global__ void rope_kernel(const float* __restrict__ in, float* __restrict__ out) {
    int idx = blockIdx.x * blockDim.x + threadIdx.x;  // < B*S*H*32 = 2^21
    int d = idx & 31;
    int h = (idx >> 5) & 15;
    int s = (idx >> 9) & 2047;
    int b = idx >> 20;
    const float* src = in + (b * SS + s) * DD + h * 64;
    float x0 = src[d];
    float x1 = src[d + 32];
    float c = g_cos[s * 32 + d];
    float sn = g_sin[s * 32 + d];
    float* dst = out + ((b * HH + h) * SS + s) * DKK;
    dst[d]      = x0 * c - x1 * sn;
    dst[d + 32] = x1 * c + x0 * sn;
}

// Transpose only (for V): [B,S,D] -> [B,H,S,DK]
__global__ void transpose_kernel(const float* __restrict__ in, float* __restrict__ out) {
    int idx = blockIdx.x * blockDim.x + threadIdx.x;  // < B*S*D = 2^23
    int c = idx & 63;
    int h = (idx >> 6) & 15;
    int s = (idx >> 10) & 2047;
    int b = idx >> 21;
    out[((b * HH + h) * SS + s) * DKK + c] = in[(b * SS + s) * DD + h * 64 + c];
}

// ---------------------------------------------------------------------------
// Flash attention (causal): per (b,h,q-tile of 64), online softmax.
// smem: Qs[64*64] | KP[64*68] (K tile, later reused for P) | Vs[64*64]
// ---------------------------------------------------------------------------
__global__ void attn_kernel() {
    extern __shared__ float sm[];
    float* Qs = sm;                   // 4096
    float* KP = sm + 4096;            // 64*68 = 4352
    float* Vs = sm + 4096 + 4352;     // 4096

    int qt = blockIdx.x;  // q tile
    int h  = blockIdx.y;
    int b  = blockIdx.z;
    int tid = threadIdx.x;
    int tx = tid & 15, ty = tid >> 4;
    int qr0 = ty * 4;     // local q rows
    int kc0 = tx * 4;     // local k cols / out cols

    const float* Qb  = g_qh + ((b * HH + h) * SS + qt * 64) * DKK;
    const float* Kb0 = g_kh + ((b * HH + h) * SS) * DKK;
    const float* Vb0 = g_vh + ((b * HH + h) * SS) * DKK;

#pragma unroll
    for (int t = 0; t < 16; t++) {
        int idx = tid + t * 256;
        Qs[idx] = Qb[idx];
    }
    __syncthreads();

    float o[4][4] = {};
    float m_i[4], l_i[4];
#pragma unroll
    for (int i = 0; i < 4; i++) { m_i[i] = -1e30f; l_i[i] = 0.0f; }

    int qglob0 = qt * 64 + qr0;

    for (int j0 = 0; j0 <= qt; j0++) {
        const float* Kb = Kb0 + j0 * 64 * DKK;
        const float* Vb = Vb0 + j0 * 64 * DKK;
#pragma unroll
        for (int t = 0; t < 16; t++) {
            int idx = tid + t * 256;
            int r = idx >> 6, c = idx & 63;
            KP[r * 68 + c] = Kb[idx];
            Vs[idx] = Vb[idx];
        }
        __syncthreads();

        // S = Q @ K^T
        float s[4][4] = {};
#pragma unroll
        for (int d = 0; d < 64; d += 4) {
            float4 qv[4], kv[4];
#pragma unroll
            for (int i = 0; i < 4; i++) qv[i] = *(const float4*)(Qs + (qr0 + i) * 64 + d);
#pragma unroll
            for (int j = 0; j < 4; j++) kv[j] = *(const float4*)(KP + (kc0 + j) * 68 + d);
#pragma unroll
            for (int i = 0; i < 4; i++)
#pragma unroll
                for (int j = 0; j < 4; j++)
                    s[i][j] += qv[i].x * kv[j].x + qv[i].y * kv[j].y +
                               qv[i].z * kv[j].z + qv[i].w * kv[j].w;
        }

        bool diag = (j0 == qt);
        float mloc[4];
#pragma unroll
        for (int i = 0; i < 4; i++) {
            float mm = -1e30f;
#pragma unroll
            for (int j = 0; j < 4; j++) {
                float v = s[i][j] * 0.125f;
                if (diag && (j0 * 64 + kc0 + j) > (qglob0 + i)) v = -1e30f;
                s[i][j] = v;
                mm = fmaxf(mm, v);
            }
            mloc[i] = mm;
        }
        // reduce max across the 16 tx lanes (within 16-lane half-warp groups)
#pragma unroll
        for (int off = 1; off < 16; off <<= 1)
#pragma unroll
            for (int i = 0; i < 4; i++)
                mloc[i] = fmaxf(mloc[i], __shfl_xor_sync(0xffffffffu, mloc[i], off));

        float p[4][4], alpha[4], lloc[4];
#pragma unroll
        for (int i = 0; i < 4; i++) {
            float mn = fmaxf(m_i[i], mloc[i]);
            alpha[i] = expf(m_i[i] - mn);
            m_i[i] = mn;
            float ssum = 0.0f;
#pragma unroll
            for (int j = 0; j < 4; j++) {
                p[i][j] = expf(s[i][j] - mn);
                ssum += p[i][j];
            }
            lloc[i] = ssum;
        }
#pragma unroll
        for (int off = 1; off < 16; off <<= 1)
#pragma unroll
            for (int i = 0; i < 4; i++)
                lloc[i] += __shfl_xor_sync(0xffffffffu, lloc[i], off);
#pragma unroll
        for (int i = 0; i < 4; i++) {
            l_i[i] = l_i[i] * alpha[i] + lloc[i];
#pragma unroll
            for (int j = 0; j < 4; j++) o[i][j] *= alpha[i];
        }

        __syncthreads();  // all done reading K before overwriting with P
#pragma unroll
        for (int i = 0; i < 4; i++)
#pragma unroll
            for (int j = 0; j < 4; j++)
                KP[(qr0 + i) * 68 + kc0 + j] = p[i][j];
        __syncthreads();

        // O += P @ V
#pragma unroll
        for (int k = 0; k < 64; k++) {
            float4 vv = *(const float4*)(Vs + k * 64 + kc0);
            float p0 = KP[(qr0 + 0) * 68 + k];
            float p1 = KP[(qr0 + 1) * 68 + k];
            float p2 = KP[(qr0 + 2) * 68 + k];
            float p3 = KP[(qr0 + 3) * 68 + k];
            o[0][0] += p0 * vv.x; o[0][1] += p0 * vv.y; o[0][2] += p0 * vv.z; o[0][3] += p0 * vv.w;
            o[1][0] += p1 * vv.x; o[1][1] += p1 * vv.y; o[1][2] += p1 * vv.z; o[1][3] += p1 * vv.w;
            o[2][0] += p2 * vv.x; o[2][1] += p2 * vv.y; o[2][2] += p2 * vv.z; o[2][3] += p2 * vv.w;
            o[3][0] += p3 * vv.x; o[3][1] += p3 * vv.y; o[3][2] += p3 * vv.z; o[3][3] += p3 * vv.w;
        }
        __syncthreads();  // done with KP/Vs before next tile load
    }

    // write [B,S,D] layout (merged head transpose)
    float* Ob = g_attn + (b * SS + qt * 64) * DD + h * DKK;
#pragma unroll
    for (int i = 0; i < 4; i++) {
        float inv = 1.0f / l_i[i];
#pragma unroll
        for (int j = 0; j < 4; j++)
            Ob[(qr0 + i) * DD + kc0 + j] = o[i][j] * inv;
    }
}

// ---------------------------------------------------------------------------
// Launch
// ---------------------------------------------------------------------------
extern "C" void kernel_launch(void* const* d_in, const int* in_sizes, int n_in,
                              void* d_out, int out_size) {
    const float* q  = (const float*)d_in[0];
    const float* k  = (const float*)d_in[1];
    const float* v  = (const float*)d_in[2];
    // d_in[3] = mask (tril, deterministic) — applied analytically
    const float* Wq = (const float*)d_in[4];
    const float* bq = (const float*)d_in[5];
    const float* Wk = (const float*)d_in[6];
    const float* bk = (const float*)d_in[7];
    const float* Wv = (const float*)d_in[8];
    const float* bv = (const float*)d_in[9];
    const float* Wo = (const float*)d_in[10];
    const float* bo = (const float*)d_in[11];
    float* out = (float*)d_out;

    float *tmpq, *tmpk, *tmpv, *qh, *kh, *vh, *attn;
    cudaGetSymbolAddress((void**)&tmpq, g_tmpq);
    cudaGetSymbolAddress((void**)&tmpk, g_tmpk);
    cudaGetSymbolAddress((void**)&tmpv, g_tmpv);
    cudaGetSymbolAddress((void**)&qh,   g_qh);
    cudaGetSymbolAddress((void**)&kh,   g_kh);
    cudaGetSymbolAddress((void**)&vh,   g_vh);
    cudaGetSymbolAddress((void**)&attn, g_attn);

    const int smem_attn = (4096 + 64 * 68 + 4096) * 4;  // 50176 B
    cudaFuncSetAttribute(attn_kernel, cudaFuncAttributeMaxDynamicSharedMemorySize, smem_attn);

    dim3 ggrid(DD / 64, (BB * SS) / 64);  // (16, 64)

    // Projections
    gemm_bias_kernel<<<ggrid, 256>>>(q, Wq, bq, tmpq);
    gemm_bias_kernel<<<ggrid, 256>>>(k, Wk, bk, tmpk);
    gemm_bias_kernel<<<ggrid, 256>>>(v, Wv, bv, tmpv);

    // RoPE tables + apply + layout transform
    rope_table_kernel<<<SS, 32>>>();
    rope_kernel<<<(BB * SS * HH * 32) / 256, 256>>>(tmpq, qh);
    rope_kernel<<<(BB * SS * HH * 32) / 256, 256>>>(tmpk, kh);
    transpose_kernel<<<(BB * SS * DD) / 256, 256>>>(tmpv, vh);

    // Attention
    attn_kernel<<<dim3(SS / 64, HH, BB), 256, smem_attn>>>();

    // Output projection
    gemm_bias_kernel<<<ggrid, 256>>>(attn, Wo, bo, out);
}

// round 4
// speedup vs baseline: 1.2825x; 1.2825x over previous
#include <cuda_runtime.h>
#include <cuda_bf16.h>
#include <cstdint>
#include <math.h>

#define BB 2
#define SS 2048
#define DD 1024
#define HH 16
#define DKK 64

#define GM 4096   // B*S rows
#define GN 1024
#define GK 1024
#define PITCH 80  // smem row pitch in bytes (16B-aligned, bank-friendly)

// ---------------------------------------------------------------------------
// Scratch (__device__ globals; no allocation allowed)
// ---------------------------------------------------------------------------
__device__ float g_tmpq[BB*SS*DD];
__device__ float g_tmpk[BB*SS*DD];
__device__ float g_tmpv[BB*SS*DD];
__device__ float g_qh[BB*SS*DD];   // [B,H,S,DK]
__device__ float g_kh[BB*SS*DD];
__device__ float g_vh[BB*SS*DD];
__device__ float g_attn[BB*SS*DD]; // [B,S,D]
__device__ float g_cos[SS*32];
__device__ float g_sin[SS*32];
__device__ __nv_bfloat16 g_whi[DD*DD];  // transposed weight, hi part [N,K]
__device__ __nv_bfloat16 g_wlo[DD*DD];  // transposed weight, lo part [N,K]

// ---------------------------------------------------------------------------
// mma.sync / ldmatrix helpers (base sm_103 ISA — no tcgen05)
// ---------------------------------------------------------------------------
__device__ __forceinline__ uint32_t smem_u32(const void* p) {
    uint32_t a;
    asm("{ .reg .u64 t; cvta.to.shared.u64 t, %1; cvt.u32.u64 %0, t; }"
        : "=r"(a) : "l"(p));
    return a;
}
__device__ __forceinline__ void ldsm_x4(uint32_t* r, uint32_t addr) {
    asm volatile("ldmatrix.sync.aligned.m8n8.x4.shared.b16 {%0,%1,%2,%3}, [%4];"
        : "=r"(r[0]), "=r"(r[1]), "=r"(r[2]), "=r"(r[3]) : "r"(addr));
}
__device__ __forceinline__ void ldsm_x2(uint32_t* r, uint32_t addr) {
    asm volatile("ldmatrix.sync.aligned.m8n8.x2.shared.b16 {%0,%1}, [%2];"
        : "=r"(r[0]), "=r"(r[1]) : "r"(addr));
}
__device__ __forceinline__ void mma_bf16(float* d, const uint32_t* a, const uint32_t* b) {
    asm volatile(
        "mma.sync.aligned.m16n8k16.row.col.f32.bf16.bf16.f32 "
        "{%0,%1,%2,%3}, {%4,%5,%6,%7}, {%8,%9}, {%0,%1,%2,%3};"
        : "+f"(d[0]), "+f"(d[1]), "+f"(d[2]), "+f"(d[3])
        : "r"(a[0]), "r"(a[1]), "r"(a[2]), "r"(a[3]), "r"(b[0]), "r"(b[1]));
}

// ---------------------------------------------------------------------------
// Weight transpose + bf16 hi/lo split: W[K,N] f32 -> Wt_hi/lo[N,K] bf16
// ---------------------------------------------------------------------------
__global__ void wsplit_kernel(const float* __restrict__ W,
                              __nv_bfloat16* __restrict__ hi,
                              __nv_bfloat16* __restrict__ lo) {
    __shared__ float t[32][33];
    int k0 = blockIdx.y * 32, n0 = blockIdx.x * 32;
    t[threadIdx.y][threadIdx.x] = W[(k0 + threadIdx.y) * DD + n0 + threadIdx.x];
    __syncthreads();
    float w = t[threadIdx.x][threadIdx.y];
    __nv_bfloat16 h = __float2bfloat16(w);
    __nv_bfloat16 l = __float2bfloat16(w - __bfloat162float(h));
    int out = (n0 + threadIdx.y) * DD + k0 + threadIdx.x;
    hi[out] = h;
    lo[out] = l;
}

// ---------------------------------------------------------------------------
// GEMM via mma.sync bf16 split: C[4096,1024] = A @ Wt^T + bias
// CTA 128x128, 8 warps (2M x 4N), warp tile 64x32, K-chunk 32.
// C = A_hi*B_hi + A_lo*B_hi + A_hi*B_lo  (fp32 accum)
// ---------------------------------------------------------------------------
#define SM_AHI 0
#define SM_ALO 10240
#define SM_BHI 20480
#define SM_BLO 30720
#define GEMM_SMEM 40960

__global__ void __launch_bounds__(256) gemm_mma_kernel(
    const float* __restrict__ A,
    const __nv_bfloat16* __restrict__ Bhi,
    const __nv_bfloat16* __restrict__ Blo,
    const float* __restrict__ bias,
    float* __restrict__ C) {
    extern __shared__ char smem[];
    uint32_t sbase = smem_u32(smem);

    int tid = threadIdx.x;
    int lane = tid & 31, w = tid >> 5;
    int wm = w & 1, wn = w >> 1;           // warp tile coords
    int bm = blockIdx.y * 128, bn = blockIdx.x * 128;

    float acc[4][4][4] = {};

    // ldmatrix source addresses (constant across chunks)
    uint32_t a_row  = wm * 64 + (lane & 15);
    uint32_t a_coff = ((lane >> 4) << 3) * 2;          // +8 cols for lanes>=16
    uint32_t b_row  = wn * 32 + (lane & 7);
    uint32_t b_coff = (((lane >> 3) & 1) << 3) * 2;    // +8 cols for odd octet

    for (int k0 = 0; k0 < GK; k0 += 32) {
        // ---- A: 128x32 f32 -> hi/lo bf16 in smem
#pragma unroll
        for (int i = 0; i < 4; i++) {
            int idx = tid + i * 256;         // 0..1023 float4 slots
            int r = idx >> 3, kq = idx & 7;
            float4 a = *(const float4*)&A[(bm + r) * GK + k0 + kq * 4];
            __nv_bfloat16 h0 = __float2bfloat16(a.x);
            __nv_bfloat16 h1 = __float2bfloat16(a.y);
            __nv_bfloat16 h2 = __float2bfloat16(a.z);
            __nv_bfloat16 h3 = __float2bfloat16(a.w);
            uint32_t hi01 = ((uint32_t)__bfloat16_as_ushort(h1) << 16) | __bfloat16_as_ushort(h0);
            uint32_t hi23 = ((uint32_t)__bfloat16_as_ushort(h3) << 16) | __bfloat16_as_ushort(h2);
            __nv_bfloat16 l0 = __float2bfloat16(a.x - __bfloat162float(h0));
            __nv_bfloat16 l1 = __float2bfloat16(a.y - __bfloat162float(h1));
            __nv_bfloat16 l2 = __float2bfloat16(a.z - __bfloat162float(h2));
            __nv_bfloat16 l3 = __float2bfloat16(a.w - __bfloat162float(h3));
            uint32_t lo01 = ((uint32_t)__bfloat16_as_ushort(l1) << 16) | __bfloat16_as_ushort(l0);
            uint32_t lo23 = ((uint32_t)__bfloat16_as_ushort(l3) << 16) | __bfloat16_as_ushort(l2);
            uint32_t off = r * PITCH + kq * 8;
            *(uint2*)(smem + SM_AHI + off) = make_uint2(hi01, hi23);
            *(uint2*)(smem + SM_ALO + off) = make_uint2(lo01, lo23);
        }
        // ---- B: 128x32 bf16 (hi & lo) from pre-split [N,K]
#pragma unroll
        for (int i = 0; i < 8; i++) {
            int idx = tid + i * 256;         // 0..2047 u32 slots
            int r = idx >> 4, ku = idx & 15;
            int g = (bn + r) * (GK / 2) + k0 / 2 + ku;
            uint32_t off = r * PITCH + ku * 4;
            *(uint32_t*)(smem + SM_BHI + off) = ((const uint32_t*)Bhi)[g];
            *(uint32_t*)(smem + SM_BLO + off) = ((const uint32_t*)Blo)[g];
        }
        __syncthreads();

        // ---- MMA over the two k16 steps
#pragma unroll
        for (int ks = 0; ks < 2; ks++) {
            uint32_t kb = ks * 32;  // byte offset of k-step
            uint32_t ah[4][4], al[4][4], bh[4][2], bl[4][2];
#pragma unroll
            for (int mi = 0; mi < 4; mi++) {
                uint32_t addr = sbase + SM_AHI + (a_row + mi * 16) * PITCH + kb + a_coff;
                ldsm_x4(ah[mi], addr);
                ldsm_x4(al[mi], addr + (SM_ALO - SM_AHI));
            }
#pragma unroll
            for (int ni = 0; ni < 4; ni++) {
                uint32_t addr = sbase + SM_BHI + (b_row + ni * 8) * PITCH + kb + b_coff;
                ldsm_x2(bh[ni], addr);
                ldsm_x2(bl[ni], addr + (SM_BLO - SM_BHI));
            }
#pragma unroll
            for (int mi = 0; mi < 4; mi++)
#pragma unroll
                for (int ni = 0; ni < 4; ni++) {
                    mma_bf16(acc[mi][ni], ah[mi], bh[ni]);
                    mma_bf16(acc[mi][ni], al[mi], bh[ni]);
                    mma_bf16(acc[mi][ni], ah[mi], bl[ni]);
                }
        }
        __syncthreads();
    }

    // ---- epilogue: regs -> gmem with bias
    int r0 = bm + wm * 64 + (lane >> 2);
    int c0 = bn + wn * 32 + (lane & 3) * 2;
#pragma unroll
    for (int mi = 0; mi < 4; mi++) {
#pragma unroll
        for (int ni = 0; ni < 4; ni++) {
            int row = r0 + mi * 16;
            int col = c0 + ni * 8;
            float b0 = bias[col], b1 = bias[col + 1];
            float2 v0 = make_float2(acc[mi][ni][0] + b0, acc[mi][ni][1] + b1);
            float2 v1 = make_float2(acc[mi][ni][2] + b0, acc[mi][ni][3] + b1);
            *(float2*)&C[row * GN + col] = v0;
            *(float2*)&C[(row + 8) * GN + col] = v1;
        }
    }
}

// ---------------------------------------------------------------------------
// RoPE tables
// ---------------------------------------------------------------------------
__global__ void rope_table_kernel() {
    int p = blockIdx.x;
    int i = threadIdx.x;  // 0..31
    double inv = exp(-((double)(2 * i) / 64.0) * log(10000.0));
    float angf = (float)((double)p * inv);
    double a = (double)angf;
    g_cos[p * 32 + i] = (float)cos(a);
    g_sin[p * 32 + i] = (float)sin(a);
}

// ---------------------------------------------------------------------------
// RoPE apply + transpose [B,S,D] -> [B,H,S,DK]
// ---------------------------------------------------------------------------
__global__ void rope_kernel(const float* __restrict__ in, float* __restrict__ out) {
    int idx = blockIdx.x * blockDim.x + threadIdx.x;
    int d = idx & 31;
    int h = (idx >> 5) & 15;
    int s = (idx >> 9) & 2047;
    int b = idx >> 20;
    const float* src = in + (b * SS + s) * DD + h * 64;
    float x0 = src[d];
    float x1 = src[d + 32];
    float c = g_cos[s * 32 + d];
    float sn = g_sin[s * 32 + d];
    float* dst = out + ((b * HH + h) * SS + s) * DKK;
    dst[d]      = x0 * c - x1 * sn;
    dst[d + 32] = x1 * c + x0 * sn;
}

__global__ void transpose_kernel(const float* __restrict__ in, float* __restrict__ out) {
    int idx = blockIdx.x * blockDim.x + threadIdx.x;
    int c = idx & 63;
    int h = (idx >> 6) & 15;
    int s = (idx >> 10) & 2047;
    int b = idx >> 21;
    out[((b * HH + h) * SS + s) * DKK + c] = in[(b * SS + s) * DD + h * 64 + c];
}

// ---------------------------------------------------------------------------
// Flash attention (causal), fp32 (unchanged from passing version)
// ---------------------------------------------------------------------------
__global__ void attn_kernel() {
    extern __shared__ float sm[];
    float* Qs = sm;
    float* KP = sm + 4096;
    float* Vs = sm + 4096 + 4352;

    int qt = blockIdx.x;
    int h  = blockIdx.y;
    int b  = blockIdx.z;
    int tid = threadIdx.x;
    int tx = tid & 15, ty = tid >> 4;
    int qr0 = ty * 4;
    int kc0 = tx * 4;

    const float* Qb  = g_qh + ((b * HH + h) * SS + qt * 64) * DKK;
    const float* Kb0 = g_kh + ((b * HH + h) * SS) * DKK;
    const float* Vb0 = g_vh + ((b * HH + h) * SS) * DKK;

#pragma unroll
    for (int t = 0; t < 16; t++) {
        int idx = tid + t * 256;
        Qs[idx] = Qb[idx];
    }
    __syncthreads();

    float o[4][4] = {};
    float m_i[4], l_i[4];
#pragma unroll
    for (int i = 0; i < 4; i++) { m_i[i] = -1e30f; l_i[i] = 0.0f; }

    int qglob0 = qt * 64 + qr0;

    for (int j0 = 0; j0 <= qt; j0++) {
        const float* Kb = Kb0 + j0 * 64 * DKK;
        const float* Vb = Vb0 + j0 * 64 * DKK;
#pragma unroll
        for (int t = 0; t < 16; t++) {
            int idx = tid + t * 256;
            int r = idx >> 6, c = idx & 63;
            KP[r * 68 + c] = Kb[idx];
            Vs[idx] = Vb[idx];
        }
        __syncthreads();

        float s[4][4] = {};
#pragma unroll
        for (int d = 0; d < 64; d += 4) {
            float4 qv[4], kv[4];
#pragma unroll
            for (int i = 0; i < 4; i++) qv[i] = *(const float4*)(Qs + (qr0 + i) * 64 + d);
#pragma unroll
            for (int j = 0; j < 4; j++) kv[j] = *(const float4*)(KP + (kc0 + j) * 68 + d);
#pragma unroll
            for (int i = 0; i < 4; i++)
#pragma unroll
                for (int j = 0; j < 4; j++)
                    s[i][j] += qv[i].x * kv[j].x + qv[i].y * kv[j].y +
                               qv[i].z * kv[j].z + qv[i].w * kv[j].w;
        }

        bool diag = (j0 == qt);
        float mloc[4];
#pragma unroll
        for (int i = 0; i < 4; i++) {
            float mm = -1e30f;
#pragma unroll
            for (int j = 0; j < 4; j++) {
                float v = s[i][j] * 0.125f;
                if (diag && (j0 * 64 + kc0 + j) > (qglob0 + i)) v = -1e30f;
                s[i][j] = v;
                mm = fmaxf(mm, v);
            }
            mloc[i] = mm;
        }
#pragma unroll
        for (int off = 1; off < 16; off <<= 1)
#pragma unroll
            for (int i = 0; i < 4; i++)
                mloc[i] = fmaxf(mloc[i], __shfl_xor_sync(0xffffffffu, mloc[i], off));

        float p[4][4], alpha[4], lloc[4];
#pragma unroll
        for (int i = 0; i < 4; i++) {
            float mn = fmaxf(m_i[i], mloc[i]);
            alpha[i] = expf(m_i[i] - mn);
            m_i[i] = mn;
            float ssum = 0.0f;
#pragma unroll
            for (int j = 0; j < 4; j++) {
                p[i][j] = expf(s[i][j] - mn);
                ssum += p[i][j];
            }
            lloc[i] = ssum;
        }
#pragma unroll
        for (int off = 1; off < 16; off <<= 1)
#pragma unroll
            for (int i = 0; i < 4; i++)
                lloc[i] += __shfl_xor_sync(0xffffffffu, lloc[i], off);
#pragma unroll
        for (int i = 0; i < 4; i++) {
            l_i[i] = l_i[i] * alpha[i] + lloc[i];
#pragma unroll
            for (int j = 0; j < 4; j++) o[i][j] *= alpha[i];
        }

        __syncthreads();
#pragma unroll
        for (int i = 0; i < 4; i++)
#pragma unroll
            for (int j = 0; j < 4; j++)
                KP[(qr0 + i) * 68 + kc0 + j] = p[i][j];
        __syncthreads();

#pragma unroll
        for (int k = 0; k < 64; k++) {
            float4 vv = *(const float4*)(Vs + k * 64 + kc0);
            float p0 = KP[(qr0 + 0) * 68 + k];
            float p1 = KP[(qr0 + 1) * 68 + k];
            float p2 = KP[(qr0 + 2) * 68 + k];
            float p3 = KP[(qr0 + 3) * 68 + k];
            o[0][0] += p0 * vv.x; o[0][1] += p0 * vv.y; o[0][2] += p0 * vv.z; o[0][3] += p0 * vv.w;
            o[1][0] += p1 * vv.x; o[1][1] += p1 * vv.y; o[1][2] += p1 * vv.z; o[1][3] += p1 * vv.w;
            o[2][0] += p2 * vv.x; o[2][1] += p2 * vv.y; o[2][2] += p2 * vv.z; o[2][3] += p2 * vv.w;
            o[3][0] += p3 * vv.x; o[3][1] += p3 * vv.y; o[3][2] += p3 * vv.z; o[3][3] += p3 * vv.w;
        }
        __syncthreads();
    }

    float* Ob = g_attn + (b * SS + qt * 64) * DD + h * DKK;
#pragma unroll
    for (int i = 0; i < 4; i++) {
        float inv = 1.0f / l_i[i];
#pragma unroll
        for (int j = 0; j < 4; j++)
            Ob[(qr0 + i) * DD + kc0 + j] = o[i][j] * inv;
    }
}

// ---------------------------------------------------------------------------
// Launch
// ---------------------------------------------------------------------------
extern "C" void kernel_launch(void* const* d_in, const int* in_sizes, int n_in,
                              void* d_out, int out_size) {
    const float* q  = (const float*)d_in[0];
    const float* k  = (const float*)d_in[1];
    const float* v  = (const float*)d_in[2];
    const float* Wq = (const float*)d_in[4];
    const float* bq = (const float*)d_in[5];
    const float* Wk = (const float*)d_in[6];
    const float* bk = (const float*)d_in[7];
    const float* Wv = (const float*)d_in[8];
    const float* bv = (const float*)d_in[9];
    const float* Wo = (const float*)d_in[10];
    const float* bo = (const float*)d_in[11];
    float* out = (float*)d_out;

    float *tmpq, *tmpk, *tmpv, *qh, *kh, *vh, *attn;
    __nv_bfloat16 *whi, *wlo;
    cudaGetSymbolAddress((void**)&tmpq, g_tmpq);
    cudaGetSymbolAddress((void**)&tmpk, g_tmpk);
    cudaGetSymbolAddress((void**)&tmpv, g_tmpv);
    cudaGetSymbolAddress((void**)&qh,   g_qh);
    cudaGetSymbolAddress((void**)&kh,   g_kh);
    cudaGetSymbolAddress((void**)&vh,   g_vh);
    cudaGetSymbolAddress((void**)&attn, g_attn);
    cudaGetSymbolAddress((void**)&whi,  g_whi);
    cudaGetSymbolAddress((void**)&wlo,  g_wlo);

    const int smem_attn = (4096 + 64 * 68 + 4096) * 4;
    cudaFuncSetAttribute(attn_kernel, cudaFuncAttributeMaxDynamicSharedMemorySize, smem_attn);
    cudaFuncSetAttribute(gemm_mma_kernel, cudaFuncAttributeMaxDynamicSharedMemorySize, GEMM_SMEM);

    dim3 wgrid(32, 32);
    dim3 wblk(32, 32);
    dim3 ggrid(GN / 128, GM / 128);  // (8, 32)

    // Q/K/V projections (mma.sync split-bf16)
    wsplit_kernel<<<wgrid, wblk>>>(Wq, whi, wlo);
    gemm_mma_kernel<<<ggrid, 256, GEMM_SMEM>>>(q, whi, wlo, bq, tmpq);
    wsplit_kernel<<<wgrid, wblk>>>(Wk, whi, wlo);
    gemm_mma_kernel<<<ggrid, 256, GEMM_SMEM>>>(k, whi, wlo, bk, tmpk);
    wsplit_kernel<<<wgrid, wblk>>>(Wv, whi, wlo);
    gemm_mma_kernel<<<ggrid, 256, GEMM_SMEM>>>(v, whi, wlo, bv, tmpv);

    // RoPE + layout
    rope_table_kernel<<<SS, 32>>>();
    rope_kernel<<<(BB * SS * HH * 32) / 256, 256>>>(tmpq, qh);
    rope_kernel<<<(BB * SS * HH * 32) / 256, 256>>>(tmpk, kh);
    transpose_kernel<<<(BB * SS * DD) / 256, 256>>>(tmpv, vh);

    // Attention (fp32 flash)
    attn_kernel<<<dim3(SS / 64, HH, BB), 256, smem_attn>>>();

    // Output projection
    wsplit_kernel<<<wgrid, wblk>>>(Wo, whi, wlo);
    gemm_mma_kernel<<<ggrid, 256, GEMM_SMEM>>>(attn, whi, wlo, bo, out);
}

// round 5
// speedup vs baseline: 2.3158x; 1.8058x over previous
#include <cuda_runtime.h>
#include <cuda_bf16.h>
#include <cstdint>
#include <math.h>

#define BB 2
#define SS 2048
#define DD 1024
#define HH 16
#define DKK 64

#define GM 4096   // B*S rows
#define GN 1024
#define GK 1024
#define PITCH 80  // gemm smem row pitch (bytes)

// ---------------------------------------------------------------------------
// Scratch (__device__ globals; no allocation allowed)
// ---------------------------------------------------------------------------
__device__ float g_tmpq[BB*SS*DD];
__device__ float g_tmpk[BB*SS*DD];
__device__ float g_tmpv[BB*SS*DD];
__device__ float g_attn[BB*SS*DD]; // [B,S,D]
__device__ float g_cos[SS*32];
__device__ float g_sin[SS*32];
__device__ __nv_bfloat16 g_whi[DD*DD];
__device__ __nv_bfloat16 g_wlo[DD*DD];
// pre-split attention operands, [B,H,S,DK]
__device__ __nv_bfloat16 g_qhi[BB*SS*DD];
__device__ __nv_bfloat16 g_qlo[BB*SS*DD];
__device__ __nv_bfloat16 g_khi[BB*SS*DD];
__device__ __nv_bfloat16 g_klo[BB*SS*DD];
__device__ __nv_bfloat16 g_vhi[BB*SS*DD];
__device__ __nv_bfloat16 g_vlo[BB*SS*DD];

// ---------------------------------------------------------------------------
// mma.sync / ldmatrix helpers
// ---------------------------------------------------------------------------
__device__ __forceinline__ uint32_t smem_u32(const void* p) {
    uint32_t a;
    asm("{ .reg .u64 t; cvta.to.shared.u64 t, %1; cvt.u32.u64 %0, t; }"
        : "=r"(a) : "l"(p));
    return a;
}
__device__ __forceinline__ void ldsm_x4(uint32_t* r, uint32_t addr) {
    asm volatile("ldmatrix.sync.aligned.m8n8.x4.shared.b16 {%0,%1,%2,%3}, [%4];"
        : "=r"(r[0]), "=r"(r[1]), "=r"(r[2]), "=r"(r[3]) : "r"(addr));
}
__device__ __forceinline__ void ldsm_x2(uint32_t* r, uint32_t addr) {
    asm volatile("ldmatrix.sync.aligned.m8n8.x2.shared.b16 {%0,%1}, [%2];"
        : "=r"(r[0]), "=r"(r[1]) : "r"(addr));
}
__device__ __forceinline__ void ldsm_x2_t(uint32_t* r, uint32_t addr) {
    asm volatile("ldmatrix.sync.aligned.m8n8.x2.trans.shared.b16 {%0,%1}, [%2];"
        : "=r"(r[0]), "=r"(r[1]) : "r"(addr));
}
__device__ __forceinline__ void mma_bf16(float* d, const uint32_t* a, const uint32_t* b) {
    asm volatile(
        "mma.sync.aligned.m16n8k16.row.col.f32.bf16.bf16.f32 "
        "{%0,%1,%2,%3}, {%4,%5,%6,%7}, {%8,%9}, {%0,%1,%2,%3};"
        : "+f"(d[0]), "+f"(d[1]), "+f"(d[2]), "+f"(d[3])
        : "r"(a[0]), "r"(a[1]), "r"(a[2]), "r"(a[3]), "r"(b[0]), "r"(b[1]));
}
__device__ __forceinline__ uint32_t pack2(__nv_bfloat16 lo, __nv_bfloat16 hi) {
    return ((uint32_t)__bfloat16_as_ushort(hi) << 16) | __bfloat16_as_ushort(lo);
}

// ---------------------------------------------------------------------------
// Weight transpose + bf16 hi/lo split
// ---------------------------------------------------------------------------
__global__ void wsplit_kernel(const float* __restrict__ W,
                              __nv_bfloat16* __restrict__ hi,
                              __nv_bfloat16* __restrict__ lo) {
    __shared__ float t[32][33];
    int k0 = blockIdx.y * 32, n0 = blockIdx.x * 32;
    t[threadIdx.y][threadIdx.x] = W[(k0 + threadIdx.y) * DD + n0 + threadIdx.x];
    __syncthreads();
    float w = t[threadIdx.x][threadIdx.y];
    __nv_bfloat16 h = __float2bfloat16(w);
    __nv_bfloat16 l = __float2bfloat16(w - __bfloat162float(h));
    int out = (n0 + threadIdx.y) * DD + k0 + threadIdx.x;
    hi[out] = h;
    lo[out] = l;
}

// ---------------------------------------------------------------------------
// GEMM via mma.sync bf16 split (unchanged from R4)
// ---------------------------------------------------------------------------
#define SM_AHI 0
#define SM_ALO 10240
#define SM_BHI 20480
#define SM_BLO 30720
#define GEMM_SMEM 40960

__global__ void __launch_bounds__(256) gemm_mma_kernel(
    const float* __restrict__ A,
    const __nv_bfloat16* __restrict__ Bhi,
    const __nv_bfloat16* __restrict__ Blo,
    const float* __restrict__ bias,
    float* __restrict__ C) {
    extern __shared__ char smem[];
    uint32_t sbase = smem_u32(smem);

    int tid = threadIdx.x;
    int lane = tid & 31, w = tid >> 5;
    int wm = w & 1, wn = w >> 1;
    int bm = blockIdx.y * 128, bn = blockIdx.x * 128;

    float acc[4][4][4] = {};

    uint32_t a_row  = wm * 64 + (lane & 15);
    uint32_t a_coff = ((lane >> 4) << 3) * 2;
    uint32_t b_row  = wn * 32 + (lane & 7);
    uint32_t b_coff = (((lane >> 3) & 1) << 3) * 2;

    for (int k0 = 0; k0 < GK; k0 += 32) {
#pragma unroll
        for (int i = 0; i < 4; i++) {
            int idx = tid + i * 256;
            int r = idx >> 3, kq = idx & 7;
            float4 a = *(const float4*)&A[(bm + r) * GK + k0 + kq * 4];
            __nv_bfloat16 h0 = __float2bfloat16(a.x);
            __nv_bfloat16 h1 = __float2bfloat16(a.y);
            __nv_bfloat16 h2 = __float2bfloat16(a.z);
            __nv_bfloat16 h3 = __float2bfloat16(a.w);
            uint32_t hi01 = pack2(h0, h1);
            uint32_t hi23 = pack2(h2, h3);
            __nv_bfloat16 l0 = __float2bfloat16(a.x - __bfloat162float(h0));
            __nv_bfloat16 l1 = __float2bfloat16(a.y - __bfloat162float(h1));
            __nv_bfloat16 l2 = __float2bfloat16(a.z - __bfloat162float(h2));
            __nv_bfloat16 l3 = __float2bfloat16(a.w - __bfloat162float(h3));
            uint32_t lo01 = pack2(l0, l1);
            uint32_t lo23 = pack2(l2, l3);
            uint32_t off = r * PITCH + kq * 8;
            *(uint2*)(smem + SM_AHI + off) = make_uint2(hi01, hi23);
            *(uint2*)(smem + SM_ALO + off) = make_uint2(lo01, lo23);
        }
#pragma unroll
        for (int i = 0; i < 8; i++) {
            int idx = tid + i * 256;
            int r = idx >> 4, ku = idx & 15;
            int g = (bn + r) * (GK / 2) + k0 / 2 + ku;
            uint32_t off = r * PITCH + ku * 4;
            *(uint32_t*)(smem + SM_BHI + off) = ((const uint32_t*)Bhi)[g];
            *(uint32_t*)(smem + SM_BLO + off) = ((const uint32_t*)Blo)[g];
        }
        __syncthreads();

#pragma unroll
        for (int ks = 0; ks < 2; ks++) {
            uint32_t kb = ks * 32;
            uint32_t ah[4][4], al[4][4], bh[4][2], bl[4][2];
#pragma unroll
            for (int mi = 0; mi < 4; mi++) {
                uint32_t addr = sbase + SM_AHI + (a_row + mi * 16) * PITCH + kb + a_coff;
                ldsm_x4(ah[mi], addr);
                ldsm_x4(al[mi], addr + (SM_ALO - SM_AHI));
            }
#pragma unroll
            for (int ni = 0; ni < 4; ni++) {
                uint32_t addr = sbase + SM_BHI + (b_row + ni * 8) * PITCH + kb + b_coff;
                ldsm_x2(bh[ni], addr);
                ldsm_x2(bl[ni], addr + (SM_BLO - SM_BHI));
            }
#pragma unroll
            for (int mi = 0; mi < 4; mi++)
#pragma unroll
                for (int ni = 0; ni < 4; ni++) {
                    mma_bf16(acc[mi][ni], ah[mi], bh[ni]);
                    mma_bf16(acc[mi][ni], al[mi], bh[ni]);
                    mma_bf16(acc[mi][ni], ah[mi], bl[ni]);
                }
        }
        __syncthreads();
    }

    int r0 = bm + wm * 64 + (lane >> 2);
    int c0 = bn + wn * 32 + (lane & 3) * 2;
#pragma unroll
    for (int mi = 0; mi < 4; mi++) {
#pragma unroll
        for (int ni = 0; ni < 4; ni++) {
            int row = r0 + mi * 16;
            int col = c0 + ni * 8;
            float b0 = bias[col], b1 = bias[col + 1];
            float2 v0 = make_float2(acc[mi][ni][0] + b0, acc[mi][ni][1] + b1);
            float2 v1 = make_float2(acc[mi][ni][2] + b0, acc[mi][ni][3] + b1);
            *(float2*)&C[row * GN + col] = v0;
            *(float2*)&C[(row + 8) * GN + col] = v1;
        }
    }
}

// ---------------------------------------------------------------------------
// RoPE tables
// ---------------------------------------------------------------------------
__global__ void rope_table_kernel() {
    int p = blockIdx.x;
    int i = threadIdx.x;
    double inv = exp(-((double)(2 * i) / 64.0) * log(10000.0));
    float angf = (float)((double)p * inv);
    double a = (double)angf;
    g_cos[p * 32 + i] = (float)cos(a);
    g_sin[p * 32 + i] = (float)sin(a);
}

// ---------------------------------------------------------------------------
// RoPE apply + transpose + bf16 hi/lo split: [B,S,D] f32 -> [B,H,S,DK] bf16x2
// ---------------------------------------------------------------------------
__global__ void rope_split_kernel(const float* __restrict__ in,
                                  __nv_bfloat16* __restrict__ hi,
                                  __nv_bfloat16* __restrict__ lo) {
    int idx = blockIdx.x * blockDim.x + threadIdx.x;
    int d = idx & 31;
    int h = (idx >> 5) & 15;
    int s = (idx >> 9) & 2047;
    int b = idx >> 20;
    const float* src = in + (b * SS + s) * DD + h * 64;
    float x0 = src[d];
    float x1 = src[d + 32];
    float c = g_cos[s * 32 + d];
    float sn = g_sin[s * 32 + d];
    float y0 = x0 * c - x1 * sn;
    float y1 = x1 * c + x0 * sn;
    int base = ((b * HH + h) * SS + s) * DKK;
    __nv_bfloat16 h0 = __float2bfloat16(y0);
    __nv_bfloat16 h1 = __float2bfloat16(y1);
    hi[base + d]      = h0;
    hi[base + d + 32] = h1;
    lo[base + d]      = __float2bfloat16(y0 - __bfloat162float(h0));
    lo[base + d + 32] = __float2bfloat16(y1 - __bfloat162float(h1));
}

__global__ void vsplit_kernel(const float* __restrict__ in,
                              __nv_bfloat16* __restrict__ hi,
                              __nv_bfloat16* __restrict__ lo) {
    int idx = blockIdx.x * blockDim.x + threadIdx.x;
    int c = idx & 63;
    int h = (idx >> 6) & 15;
    int s = (idx >> 10) & 2047;
    int b = idx >> 21;
    float v = in[(b * SS + s) * DD + h * 64 + c];
    int o = ((b * HH + h) * SS + s) * DKK + c;
    __nv_bfloat16 hh = __float2bfloat16(v);
    hi[o] = hh;
    lo[o] = __float2bfloat16(v - __bfloat162float(hh));
}

// ---------------------------------------------------------------------------
// Flash attention on mma.sync, split-bf16. Q tile 128 x KV tile 64.
// 8 warps, warp owns 16 q rows. Causal.
// ---------------------------------------------------------------------------
#define APITCH 144
#define AS_QHI 0
#define AS_QLO 18432            // 128*144
#define AS_KHI 36864
#define AS_KLO (36864 + 9216)
#define AS_VHI (36864 + 2*9216)
#define AS_VLO (36864 + 3*9216)
#define ATTN_SMEM (36864 + 4*9216)   // 73728

__global__ void __launch_bounds__(256) attn_mma_kernel() {
    extern __shared__ char smem[];
    uint32_t sbase = smem_u32(smem);
    int tid = threadIdx.x;
    int lane = tid & 31, w = tid >> 5;
    int qt = blockIdx.x, h = blockIdx.y, b = blockIdx.z;

    size_t hb   = (size_t)(b * HH + h) * SS * DKK;     // head base (elems)
    size_t qoff = hb + (size_t)qt * 128 * DKK;

    // ---- stage Q hi/lo into smem (1024 uint4 per array)
    {
        const uint4* qh4 = (const uint4*)g_qhi + qoff / 8;
        const uint4* ql4 = (const uint4*)g_qlo + qoff / 8;
#pragma unroll
        for (int i = 0; i < 8; i++) {
            int idx = tid + i * 256;       // 0..2047
            int arr = idx >> 10;           // const per i
            int s2 = idx & 1023;
            int r = s2 >> 3, c = s2 & 7;
            uint4 v = (arr ? ql4 : qh4)[r * 8 + c];
            *(uint4*)(smem + (arr ? AS_QLO : AS_QHI) + r * APITCH + c * 16) = v;
        }
    }
    __syncthreads();

    // ---- preload Q fragments (4 k-steps x 4 regs, hi & lo)
    uint32_t qfh[4][4], qfl[4][4];
    {
        uint32_t arow = w * 16 + (lane & 15);
        uint32_t acoff = (lane >> 4) * 16;
#pragma unroll
        for (int ks = 0; ks < 4; ks++) {
            uint32_t addr = sbase + AS_QHI + arow * APITCH + ks * 32 + acoff;
            ldsm_x4(qfh[ks], addr);
            ldsm_x4(qfl[ks], addr + (AS_QLO - AS_QHI));
        }
    }

    float o[8][4] = {};
    float m0 = -1e30f, m1 = -1e30f, l0 = 0.0f, l1 = 0.0f;
    int row0 = qt * 128 + w * 16 + (lane >> 2);
    int row1 = row0 + 8;

    int jmax = 2 * qt + 1;
    for (int j0 = 0; j0 <= jmax; j0++) {
        // ---- stage K/V hi/lo tiles (512 uint4 per array, 4 arrays)
        {
            size_t kvb = (hb + (size_t)j0 * 64 * DKK) / 8;
#pragma unroll
            for (int i = 0; i < 8; i++) {
                int idx = tid + i * 256;   // 0..2047
                int arr = idx >> 9;        // const per i: 0 khi,1 klo,2 vhi,3 vlo
                int s2 = idx & 511;
                int r = s2 >> 3, c = s2 & 7;
                const uint4* src = (arr == 0) ? (const uint4*)g_khi :
                                   (arr == 1) ? (const uint4*)g_klo :
                                   (arr == 2) ? (const uint4*)g_vhi :
                                                (const uint4*)g_vlo;
                uint4 v = src[kvb + r * 8 + c];
                *(uint4*)(smem + AS_KHI + arr * 9216 + r * APITCH + c * 16) = v;
            }
        }
        __syncthreads();

        // ---- S = Q K^T (split)
        float sacc[8][4] = {};
#pragma unroll
        for (int ks = 0; ks < 4; ks++) {
#pragma unroll
            for (int nt = 0; nt < 8; nt++) {
                uint32_t kh2[2], kl2[2];
                uint32_t kaddr = sbase + AS_KHI + (nt * 8 + (lane & 7)) * APITCH
                               + ks * 32 + ((lane >> 3) & 1) * 16;
                ldsm_x2(kh2, kaddr);
                ldsm_x2(kl2, kaddr + (AS_KLO - AS_KHI));
                mma_bf16(sacc[nt], qfh[ks], kh2);
                mma_bf16(sacc[nt], qfl[ks], kh2);
                mma_bf16(sacc[nt], qfh[ks], kl2);
            }
        }

        // ---- softmax (online)
        bool domask = (j0 >= 2 * qt);
        int colb = j0 * 64 + (lane & 3) * 2;
        float mx0 = -1e30f, mx1 = -1e30f;
#pragma unroll
        for (int nt = 0; nt < 8; nt++) {
            float s0 = sacc[nt][0] * 0.125f;
            float s1 = sacc[nt][1] * 0.125f;
            float s2 = sacc[nt][2] * 0.125f;
            float s3 = sacc[nt][3] * 0.125f;
            if (domask) {
                int c0 = colb + nt * 8;
                if (c0     > row0) s0 = -1e30f;
                if (c0 + 1 > row0) s1 = -1e30f;
                if (c0     > row1) s2 = -1e30f;
                if (c0 + 1 > row1) s3 = -1e30f;
            }
            sacc[nt][0] = s0; sacc[nt][1] = s1;
            sacc[nt][2] = s2; sacc[nt][3] = s3;
            mx0 = fmaxf(mx0, fmaxf(s0, s1));
            mx1 = fmaxf(mx1, fmaxf(s2, s3));
        }
        mx0 = fmaxf(mx0, __shfl_xor_sync(0xffffffffu, mx0, 1));
        mx0 = fmaxf(mx0, __shfl_xor_sync(0xffffffffu, mx0, 2));
        mx1 = fmaxf(mx1, __shfl_xor_sync(0xffffffffu, mx1, 1));
        mx1 = fmaxf(mx1, __shfl_xor_sync(0xffffffffu, mx1, 2));

        float mn0 = fmaxf(m0, mx0), mn1 = fmaxf(m1, mx1);
        float al0 = __expf(m0 - mn0), al1 = __expf(m1 - mn1);
        m0 = mn0; m1 = mn1;

        uint32_t phi[8][2], plo[8][2];
        float ls0 = 0.0f, ls1 = 0.0f;
#pragma unroll
        for (int nt = 0; nt < 8; nt++) {
            float p0 = __expf(sacc[nt][0] - mn0);
            float p1 = __expf(sacc[nt][1] - mn0);
            float p2 = __expf(sacc[nt][2] - mn1);
            float p3 = __expf(sacc[nt][3] - mn1);
            ls0 += p0 + p1; ls1 += p2 + p3;
            __nv_bfloat16 h0 = __float2bfloat16(p0);
            __nv_bfloat16 h1 = __float2bfloat16(p1);
            __nv_bfloat16 h2 = __float2bfloat16(p2);
            __nv_bfloat16 h3 = __float2bfloat16(p3);
            phi[nt][0] = pack2(h0, h1);
            phi[nt][1] = pack2(h2, h3);
            plo[nt][0] = pack2(__float2bfloat16(p0 - __bfloat162float(h0)),
                               __float2bfloat16(p1 - __bfloat162float(h1)));
            plo[nt][1] = pack2(__float2bfloat16(p2 - __bfloat162float(h2)),
                               __float2bfloat16(p3 - __bfloat162float(h3)));
        }
        l0 = l0 * al0 + ls0;
        l1 = l1 * al1 + ls1;
#pragma unroll
        for (int nt = 0; nt < 8; nt++) {
            o[nt][0] *= al0; o[nt][1] *= al0;
            o[nt][2] *= al1; o[nt][3] *= al1;
        }

        // ---- O += P V (split P, split V)
#pragma unroll
        for (int ks = 0; ks < 4; ks++) {
            uint32_t pah[4] = {phi[2*ks][0], phi[2*ks][1], phi[2*ks+1][0], phi[2*ks+1][1]};
            uint32_t pal[4] = {plo[2*ks][0], plo[2*ks][1], plo[2*ks+1][0], plo[2*ks+1][1]};
#pragma unroll
            for (int dn = 0; dn < 8; dn++) {
                uint32_t vh2[2], vl2[2];
                uint32_t vaddr = sbase + AS_VHI
                    + (ks * 16 + (lane & 7) + ((lane >> 3) & 1) * 8) * APITCH + dn * 16;
                ldsm_x2_t(vh2, vaddr);
                ldsm_x2_t(vl2, vaddr + (AS_VLO - AS_VHI));
                mma_bf16(o[dn], pah, vh2);
                mma_bf16(o[dn], pal, vh2);
                mma_bf16(o[dn], pah, vl2);
            }
        }
        __syncthreads();
    }

    // ---- epilogue: normalize and write [B,S,D]
    float lr0 = l0 + __shfl_xor_sync(0xffffffffu, l0, 1);
    lr0 += __shfl_xor_sync(0xffffffffu, lr0, 2);
    float lr1 = l1 + __shfl_xor_sync(0xffffffffu, l1, 1);
    lr1 += __shfl_xor_sync(0xffffffffu, lr1, 2);
    float inv0 = 1.0f / lr0, inv1 = 1.0f / lr1;

    float* O0 = g_attn + ((size_t)b * SS + row0) * DD + h * 64;
    float* O1 = g_attn + ((size_t)b * SS + row1) * DD + h * 64;
#pragma unroll
    for (int dn = 0; dn < 8; dn++) {
        int col = dn * 8 + (lane & 3) * 2;
        *(float2*)&O0[col] = make_float2(o[dn][0] * inv0, o[dn][1] * inv0);
        *(float2*)&O1[col] = make_float2(o[dn][2] * inv1, o[dn][3] * inv1);
    }
}

// ---------------------------------------------------------------------------
// Launch
// ---------------------------------------------------------------------------
extern "C" void kernel_launch(void* const* d_in, const int* in_sizes, int n_in,
                              void* d_out, int out_size) {
    const float* q  = (const float*)d_in[0];
    const float* k  = (const float*)d_in[1];
    const float* v  = (const float*)d_in[2];
    const float* Wq = (const float*)d_in[4];
    const float* bq = (const float*)d_in[5];
    const float* Wk = (const float*)d_in[6];
    const float* bk = (const float*)d_in[7];
    const float* Wv = (const float*)d_in[8];
    const float* bv = (const float*)d_in[9];
    const float* Wo = (const float*)d_in[10];
    const float* bo = (const float*)d_in[11];
    float* out = (float*)d_out;

    float *tmpq, *tmpk, *tmpv, *attn;
    __nv_bfloat16 *whi, *wlo, *qhi, *qlo, *khi, *klo, *vhi, *vlo;
    cudaGetSymbolAddress((void**)&tmpq, g_tmpq);
    cudaGetSymbolAddress((void**)&tmpk, g_tmpk);
    cudaGetSymbolAddress((void**)&tmpv, g_tmpv);
    cudaGetSymbolAddress((void**)&attn, g_attn);
    cudaGetSymbolAddress((void**)&whi,  g_whi);
    cudaGetSymbolAddress((void**)&wlo,  g_wlo);
    cudaGetSymbolAddress((void**)&qhi,  g_qhi);
    cudaGetSymbolAddress((void**)&qlo,  g_qlo);
    cudaGetSymbolAddress((void**)&khi,  g_khi);
    cudaGetSymbolAddress((void**)&klo,  g_klo);
    cudaGetSymbolAddress((void**)&vhi,  g_vhi);
    cudaGetSymbolAddress((void**)&vlo,  g_vlo);

    cudaFuncSetAttribute(gemm_mma_kernel, cudaFuncAttributeMaxDynamicSharedMemorySize, GEMM_SMEM);
    cudaFuncSetAttribute(attn_mma_kernel, cudaFuncAttributeMaxDynamicSharedMemorySize, ATTN_SMEM);

    dim3 wgrid(32, 32);
    dim3 wblk(32, 32);
    dim3 ggrid(GN / 128, GM / 128);

    // Q/K/V projections
    wsplit_kernel<<<wgrid, wblk>>>(Wq, whi, wlo);
    gemm_mma_kernel<<<ggrid, 256, GEMM_SMEM>>>(q, whi, wlo, bq, tmpq);
    wsplit_kernel<<<wgrid, wblk>>>(Wk, whi, wlo);
    gemm_mma_kernel<<<ggrid, 256, GEMM_SMEM>>>(k, whi, wlo, bk, tmpk);
    wsplit_kernel<<<wgrid, wblk>>>(Wv, whi, wlo);
    gemm_mma_kernel<<<ggrid, 256, GEMM_SMEM>>>(v, whi, wlo, bv, tmpv);

    // RoPE + split to bf16 hi/lo [B,H,S,DK]
    rope_table_kernel<<<SS, 32>>>();
    rope_split_kernel<<<(BB * SS * HH * 32) / 256, 256>>>(tmpq, qhi, qlo);
    rope_split_kernel<<<(BB * SS * HH * 32) / 256, 256>>>(tmpk, khi, klo);
    vsplit_kernel<<<(BB * SS * DD) / 256, 256>>>(tmpv, vhi, vlo);

    // Attention on tensor cores
    attn_mma_kernel<<<dim3(SS / 128, HH, BB), 256, ATTN_SMEM>>>();

    // Output projection
    wsplit_kernel<<<wgrid, wblk>>>(Wo, whi, wlo);
    gemm_mma_kernel<<<ggrid, 256, GEMM_SMEM>>>(attn, whi, wlo, bo, out);
}

// round 6
// speedup vs baseline: 2.9652x; 1.2804x over previous
#include <cuda_runtime.h>
#include <cuda_bf16.h>
#include <cstdint>
#include <math.h>

#define BB 2
#define SS 2048
#define DD 1024
#define HH 16
#define DKK 64

#define GM 4096   // B*S rows
#define GN 1024
#define GK 1024
#define PITCH 80  // gemm smem row pitch (bytes)

// ---------------------------------------------------------------------------
// Scratch (__device__ globals; no allocation allowed)
// ---------------------------------------------------------------------------
__device__ float g_tmpq[BB*SS*DD];
__device__ float g_tmpk[BB*SS*DD];
__device__ float g_tmpv[BB*SS*DD];
__device__ float g_attn[BB*SS*DD]; // [B,S,D]
__device__ float g_cos[SS*32];
__device__ float g_sin[SS*32];
__device__ __nv_bfloat16 g_whi[DD*DD];
__device__ __nv_bfloat16 g_wlo[DD*DD];
__device__ __nv_bfloat16 g_ahi[GM*GK];   // pre-split activation
__device__ __nv_bfloat16 g_alo[GM*GK];
// pre-split attention operands, [B,H,S,DK]
__device__ __nv_bfloat16 g_qhi[BB*SS*DD];
__device__ __nv_bfloat16 g_qlo[BB*SS*DD];
__device__ __nv_bfloat16 g_khi[BB*SS*DD];
__device__ __nv_bfloat16 g_klo[BB*SS*DD];
__device__ __nv_bfloat16 g_vhi[BB*SS*DD];
__device__ __nv_bfloat16 g_vlo[BB*SS*DD];

// ---------------------------------------------------------------------------
// mma.sync / ldmatrix / cp.async helpers
// ---------------------------------------------------------------------------
__device__ __forceinline__ uint32_t smem_u32(const void* p) {
    uint32_t a;
    asm("{ .reg .u64 t; cvta.to.shared.u64 t, %1; cvt.u32.u64 %0, t; }"
        : "=r"(a) : "l"(p));
    return a;
}
__device__ __forceinline__ void ldsm_x4(uint32_t* r, uint32_t addr) {
    asm volatile("ldmatrix.sync.aligned.m8n8.x4.shared.b16 {%0,%1,%2,%3}, [%4];"
        : "=r"(r[0]), "=r"(r[1]), "=r"(r[2]), "=r"(r[3]) : "r"(addr));
}
__device__ __forceinline__ void ldsm_x2(uint32_t* r, uint32_t addr) {
    asm volatile("ldmatrix.sync.aligned.m8n8.x2.shared.b16 {%0,%1}, [%2];"
        : "=r"(r[0]), "=r"(r[1]) : "r"(addr));
}
__device__ __forceinline__ void ldsm_x2_t(uint32_t* r, uint32_t addr) {
    asm volatile("ldmatrix.sync.aligned.m8n8.x2.trans.shared.b16 {%0,%1}, [%2];"
        : "=r"(r[0]), "=r"(r[1]) : "r"(addr));
}
__device__ __forceinline__ void mma_bf16(float* d, const uint32_t* a, const uint32_t* b) {
    asm volatile(
        "mma.sync.aligned.m16n8k16.row.col.f32.bf16.bf16.f32 "
        "{%0,%1,%2,%3}, {%4,%5,%6,%7}, {%8,%9}, {%0,%1,%2,%3};"
        : "+f"(d[0]), "+f"(d[1]), "+f"(d[2]), "+f"(d[3])
        : "r"(a[0]), "r"(a[1]), "r"(a[2]), "r"(a[3]), "r"(b[0]), "r"(b[1]));
}
__device__ __forceinline__ uint32_t pack2(__nv_bfloat16 lo, __nv_bfloat16 hi) {
    return ((uint32_t)__bfloat16_as_ushort(hi) << 16) | __bfloat16_as_ushort(lo);
}
__device__ __forceinline__ void cp_async16(uint32_t dst, const void* src) {
    asm volatile("cp.async.cg.shared.global [%0], [%1], 16;"
        :: "r"(dst), "l"(src));
}
__device__ __forceinline__ void cp_commit() {
    asm volatile("cp.async.commit_group;");
}
__device__ __forceinline__ void cp_wait0() {
    asm volatile("cp.async.wait_group 0;");
}

// ---------------------------------------------------------------------------
// Weight transpose + bf16 hi/lo split
// ---------------------------------------------------------------------------
__global__ void wsplit_kernel(const float* __restrict__ W,
                              __nv_bfloat16* __restrict__ hi,
                              __nv_bfloat16* __restrict__ lo) {
    __shared__ float t[32][33];
    int k0 = blockIdx.y * 32, n0 = blockIdx.x * 32;
    t[threadIdx.y][threadIdx.x] = W[(k0 + threadIdx.y) * DD + n0 + threadIdx.x];
    __syncthreads();
    float w = t[threadIdx.x][threadIdx.y];
    __nv_bfloat16 h = __float2bfloat16(w);
    __nv_bfloat16 l = __float2bfloat16(w - __bfloat162float(h));
    int out = (n0 + threadIdx.y) * DD + k0 + threadIdx.x;
    hi[out] = h;
    lo[out] = l;
}

// ---------------------------------------------------------------------------
// Activation bf16 hi/lo split (no transpose): f32[M,K] -> bf16 hi/lo[M,K]
// ---------------------------------------------------------------------------
__global__ void asplit_kernel(const float4* __restrict__ in,
                              uint2* __restrict__ hi,
                              uint2* __restrict__ lo) {
    int idx = blockIdx.x * blockDim.x + threadIdx.x;  // over float4 groups
    float4 a = in[idx];
    __nv_bfloat16 h0 = __float2bfloat16(a.x);
    __nv_bfloat16 h1 = __float2bfloat16(a.y);
    __nv_bfloat16 h2 = __float2bfloat16(a.z);
    __nv_bfloat16 h3 = __float2bfloat16(a.w);
    hi[idx] = make_uint2(pack2(h0, h1), pack2(h2, h3));
    lo[idx] = make_uint2(
        pack2(__float2bfloat16(a.x - __bfloat162float(h0)),
              __float2bfloat16(a.y - __bfloat162float(h1))),
        pack2(__float2bfloat16(a.z - __bfloat162float(h2)),
              __float2bfloat16(a.w - __bfloat162float(h3))));
}

// ---------------------------------------------------------------------------
// GEMM v2: pre-split bf16 operands, cp.async double-buffered.
// C[4096,1024] = A @ B^T + bias.  CTA 128x128, BK=32, 8 warps.
// C = Ah*Bh + Al*Bh + Ah*Bl  (fp32 accum)
// ---------------------------------------------------------------------------
#define STAGE_SZ 40960   // 4 arrays * 128 * 80
#define GEMM_SMEM (2 * STAGE_SZ)

__global__ void __launch_bounds__(256) gemm_mma2_kernel(
    const __nv_bfloat16* __restrict__ Ahi,
    const __nv_bfloat16* __restrict__ Alo,
    const __nv_bfloat16* __restrict__ Bhi,
    const __nv_bfloat16* __restrict__ Blo,
    const float* __restrict__ bias,
    float* __restrict__ C) {
    extern __shared__ char smem[];
    uint32_t sbase = smem_u32(smem);

    int tid = threadIdx.x;
    int lane = tid & 31, w = tid >> 5;
    int wm = w & 1, wn = w >> 1;
    int bm = blockIdx.y * 128, bn = blockIdx.x * 128;

    float acc[4][4][4] = {};

    uint32_t a_row  = wm * 64 + (lane & 15);
    uint32_t a_coff = ((lane >> 4) << 3) * 2;
    uint32_t b_row  = wn * 32 + (lane & 7);
    uint32_t b_coff = (((lane >> 3) & 1) << 3) * 2;

    // per-thread cp.async mapping: 8 ops; idx = tid + i*256 in [0,2048)
    // arr = idx>>9 (0 Ahi, 1 Alo, 2 Bhi, 3 Blo); s = idx&511; r=s>>2; c=s&3
    const __nv_bfloat16* srcs[4] = {Ahi, Alo, Bhi, Blo};

    auto load_stage = [&](int k0, int stage) {
#pragma unroll
        for (int i = 0; i < 8; i++) {
            int idx = tid + i * 256;
            int arr = idx >> 9;
            int s = idx & 511;
            int r = s >> 2, c = s & 3;
            int grow = (arr < 2 ? bm : bn) + r;
            const __nv_bfloat16* src = srcs[arr] + (size_t)grow * GK + k0 + c * 8;
            uint32_t dst = sbase + stage * STAGE_SZ + arr * 10240 + r * PITCH + c * 16;
            cp_async16(dst, src);
        }
        cp_commit();
    };

    load_stage(0, 0);
    int buf = 0;
    const int NC = GK / 32;

    for (int c = 0; c < NC; c++) {
        cp_wait0();
        __syncthreads();
        if (c + 1 < NC) load_stage((c + 1) * 32, buf ^ 1);

        uint32_t stb = sbase + buf * STAGE_SZ;
#pragma unroll
        for (int ks = 0; ks < 2; ks++) {
            uint32_t kb = ks * 32;
            uint32_t ah[4][4], al[4][4], bh[4][2], bl[4][2];
#pragma unroll
            for (int mi = 0; mi < 4; mi++) {
                uint32_t addr = stb + (a_row + mi * 16) * PITCH + kb + a_coff;
                ldsm_x4(ah[mi], addr);
                ldsm_x4(al[mi], addr + 10240);
            }
#pragma unroll
            for (int ni = 0; ni < 4; ni++) {
                uint32_t addr = stb + 20480 + (b_row + ni * 8) * PITCH + kb + b_coff;
                ldsm_x2(bh[ni], addr);
                ldsm_x2(bl[ni], addr + 10240);
            }
#pragma unroll
            for (int mi = 0; mi < 4; mi++)
#pragma unroll
                for (int ni = 0; ni < 4; ni++) {
                    mma_bf16(acc[mi][ni], ah[mi], bh[ni]);
                    mma_bf16(acc[mi][ni], al[mi], bh[ni]);
                    mma_bf16(acc[mi][ni], ah[mi], bl[ni]);
                }
        }
        buf ^= 1;
    }

    int r0 = bm + wm * 64 + (lane >> 2);
    int c0 = bn + wn * 32 + (lane & 3) * 2;
#pragma unroll
    for (int mi = 0; mi < 4; mi++) {
#pragma unroll
        for (int ni = 0; ni < 4; ni++) {
            int row = r0 + mi * 16;
            int col = c0 + ni * 8;
            float b0 = bias[col], b1 = bias[col + 1];
            float2 v0 = make_float2(acc[mi][ni][0] + b0, acc[mi][ni][1] + b1);
            float2 v1 = make_float2(acc[mi][ni][2] + b0, acc[mi][ni][3] + b1);
            *(float2*)&C[row * GN + col] = v0;
            *(float2*)&C[(row + 8) * GN + col] = v1;
        }
    }
}

// ---------------------------------------------------------------------------
// RoPE tables
// ---------------------------------------------------------------------------
__global__ void rope_table_kernel() {
    int p = blockIdx.x;
    int i = threadIdx.x;
    double inv = exp(-((double)(2 * i) / 64.0) * log(10000.0));
    float angf = (float)((double)p * inv);
    double a = (double)angf;
    g_cos[p * 32 + i] = (float)cos(a);
    g_sin[p * 32 + i] = (float)sin(a);
}

// ---------------------------------------------------------------------------
// RoPE apply + transpose + bf16 hi/lo split
// ---------------------------------------------------------------------------
__global__ void rope_split_kernel(const float* __restrict__ in,
                                  __nv_bfloat16* __restrict__ hi,
                                  __nv_bfloat16* __restrict__ lo) {
    int idx = blockIdx.x * blockDim.x + threadIdx.x;
    int d = idx & 31;
    int h = (idx >> 5) & 15;
    int s = (idx >> 9) & 2047;
    int b = idx >> 20;
    const float* src = in + (b * SS + s) * DD + h * 64;
    float x0 = src[d];
    float x1 = src[d + 32];
    float c = g_cos[s * 32 + d];
    float sn = g_sin[s * 32 + d];
    float y0 = x0 * c - x1 * sn;
    float y1 = x1 * c + x0 * sn;
    int base = ((b * HH + h) * SS + s) * DKK;
    __nv_bfloat16 h0 = __float2bfloat16(y0);
    __nv_bfloat16 h1 = __float2bfloat16(y1);
    hi[base + d]      = h0;
    hi[base + d + 32] = h1;
    lo[base + d]      = __float2bfloat16(y0 - __bfloat162float(h0));
    lo[base + d + 32] = __float2bfloat16(y1 - __bfloat162float(h1));
}

__global__ void vsplit_kernel(const float* __restrict__ in,
                              __nv_bfloat16* __restrict__ hi,
                              __nv_bfloat16* __restrict__ lo) {
    int idx = blockIdx.x * blockDim.x + threadIdx.x;
    int c = idx & 63;
    int h = (idx >> 6) & 15;
    int s = (idx >> 10) & 2047;
    int b = idx >> 21;
    float v = in[(b * SS + s) * DD + h * 64 + c];
    int o = ((b * HH + h) * SS + s) * DKK + c;
    __nv_bfloat16 hh = __float2bfloat16(v);
    hi[o] = hh;
    lo[o] = __float2bfloat16(v - __bfloat162float(hh));
}

// ---------------------------------------------------------------------------
// Flash attention on mma.sync, split-bf16 (unchanged from R5)
// ---------------------------------------------------------------------------
#define APITCH 144
#define AS_QHI 0
#define AS_QLO 18432
#define AS_KHI 36864
#define AS_KLO (36864 + 9216)
#define AS_VHI (36864 + 2*9216)
#define AS_VLO (36864 + 3*9216)
#define ATTN_SMEM (36864 + 4*9216)

__global__ void __launch_bounds__(256) attn_mma_kernel() {
    extern __shared__ char smem[];
    uint32_t sbase = smem_u32(smem);
    int tid = threadIdx.x;
    int lane = tid & 31, w = tid >> 5;
    int qt = blockIdx.x, h = blockIdx.y, b = blockIdx.z;

    size_t hb   = (size_t)(b * HH + h) * SS * DKK;
    size_t qoff = hb + (size_t)qt * 128 * DKK;

    {
        const uint4* qh4 = (const uint4*)g_qhi + qoff / 8;
        const uint4* ql4 = (const uint4*)g_qlo + qoff / 8;
#pragma unroll
        for (int i = 0; i < 8; i++) {
            int idx = tid + i * 256;
            int arr = idx >> 10;
            int s2 = idx & 1023;
            int r = s2 >> 3, c = s2 & 7;
            uint4 v = (arr ? ql4 : qh4)[r * 8 + c];
            *(uint4*)(smem + (arr ? AS_QLO : AS_QHI) + r * APITCH + c * 16) = v;
        }
    }
    __syncthreads();

    uint32_t qfh[4][4], qfl[4][4];
    {
        uint32_t arow = w * 16 + (lane & 15);
        uint32_t acoff = (lane >> 4) * 16;
#pragma unroll
        for (int ks = 0; ks < 4; ks++) {
            uint32_t addr = sbase + AS_QHI + arow * APITCH + ks * 32 + acoff;
            ldsm_x4(qfh[ks], addr);
            ldsm_x4(qfl[ks], addr + (AS_QLO - AS_QHI));
        }
    }

    float o[8][4] = {};
    float m0 = -1e30f, m1 = -1e30f, l0 = 0.0f, l1 = 0.0f;
    int row0 = qt * 128 + w * 16 + (lane >> 2);
    int row1 = row0 + 8;

    int jmax = 2 * qt + 1;
    for (int j0 = 0; j0 <= jmax; j0++) {
        {
            size_t kvb = (hb + (size_t)j0 * 64 * DKK) / 8;
#pragma unroll
            for (int i = 0; i < 8; i++) {
                int idx = tid + i * 256;
                int arr = idx >> 9;
                int s2 = idx & 511;
                int r = s2 >> 3, c = s2 & 7;
                const uint4* src = (arr == 0) ? (const uint4*)g_khi :
                                   (arr == 1) ? (const uint4*)g_klo :
                                   (arr == 2) ? (const uint4*)g_vhi :
                                                (const uint4*)g_vlo;
                uint4 v = src[kvb + r * 8 + c];
                *(uint4*)(smem + AS_KHI + arr * 9216 + r * APITCH + c * 16) = v;
            }
        }
        __syncthreads();

        float sacc[8][4] = {};
#pragma unroll
        for (int ks = 0; ks < 4; ks++) {
#pragma unroll
            for (int nt = 0; nt < 8; nt++) {
                uint32_t kh2[2], kl2[2];
                uint32_t kaddr = sbase + AS_KHI + (nt * 8 + (lane & 7)) * APITCH
                               + ks * 32 + ((lane >> 3) & 1) * 16;
                ldsm_x2(kh2, kaddr);
                ldsm_x2(kl2, kaddr + (AS_KLO - AS_KHI));
                mma_bf16(sacc[nt], qfh[ks], kh2);
                mma_bf16(sacc[nt], qfl[ks], kh2);
                mma_bf16(sacc[nt], qfh[ks], kl2);
            }
        }

        bool domask = (j0 >= 2 * qt);
        int colb = j0 * 64 + (lane & 3) * 2;
        float mx0 = -1e30f, mx1 = -1e30f;
#pragma unroll
        for (int nt = 0; nt < 8; nt++) {
            float s0 = sacc[nt][0] * 0.125f;
            float s1 = sacc[nt][1] * 0.125f;
            float s2 = sacc[nt][2] * 0.125f;
            float s3 = sacc[nt][3] * 0.125f;
            if (domask) {
                int c0 = colb + nt * 8;
                if (c0     > row0) s0 = -1e30f;
                if (c0 + 1 > row0) s1 = -1e30f;
                if (c0     > row1) s2 = -1e30f;
                if (c0 + 1 > row1) s3 = -1e30f;
            }
            sacc[nt][0] = s0; sacc[nt][1] = s1;
            sacc[nt][2] = s2; sacc[nt][3] = s3;
            mx0 = fmaxf(mx0, fmaxf(s0, s1));
            mx1 = fmaxf(mx1, fmaxf(s2, s3));
        }
        mx0 = fmaxf(mx0, __shfl_xor_sync(0xffffffffu, mx0, 1));
        mx0 = fmaxf(mx0, __shfl_xor_sync(0xffffffffu, mx0, 2));
        mx1 = fmaxf(mx1, __shfl_xor_sync(0xffffffffu, mx1, 1));
        mx1 = fmaxf(mx1, __shfl_xor_sync(0xffffffffu, mx1, 2));

        float mn0 = fmaxf(m0, mx0), mn1 = fmaxf(m1, mx1);
        float al0 = __expf(m0 - mn0), al1 = __expf(m1 - mn1);
        m0 = mn0; m1 = mn1;

        uint32_t phi[8][2], plo[8][2];
        float ls0 = 0.0f, ls1 = 0.0f;
#pragma unroll
        for (int nt = 0; nt < 8; nt++) {
            float p0 = __expf(sacc[nt][0] - mn0);
            float p1 = __expf(sacc[nt][1] - mn0);
            float p2 = __expf(sacc[nt][2] - mn1);
            float p3 = __expf(sacc[nt][3] - mn1);
            ls0 += p0 + p1; ls1 += p2 + p3;
            __nv_bfloat16 h0 = __float2bfloat16(p0);
            __nv_bfloat16 h1 = __float2bfloat16(p1);
            __nv_bfloat16 h2 = __float2bfloat16(p2);
            __nv_bfloat16 h3 = __float2bfloat16(p3);
            phi[nt][0] = pack2(h0, h1);
            phi[nt][1] = pack2(h2, h3);
            plo[nt][0] = pack2(__float2bfloat16(p0 - __bfloat162float(h0)),
                               __float2bfloat16(p1 - __bfloat162float(h1)));
            plo[nt][1] = pack2(__float2bfloat16(p2 - __bfloat162float(h2)),
                               __float2bfloat16(p3 - __bfloat162float(h3)));
        }
        l0 = l0 * al0 + ls0;
        l1 = l1 * al1 + ls1;
#pragma unroll
        for (int nt = 0; nt < 8; nt++) {
            o[nt][0] *= al0; o[nt][1] *= al0;
            o[nt][2] *= al1; o[nt][3] *= al1;
        }

#pragma unroll
        for (int ks = 0; ks < 4; ks++) {
            uint32_t pah[4] = {phi[2*ks][0], phi[2*ks][1], phi[2*ks+1][0], phi[2*ks+1][1]};
            uint32_t pal[4] = {plo[2*ks][0], plo[2*ks][1], plo[2*ks+1][0], plo[2*ks+1][1]};
#pragma unroll
            for (int dn = 0; dn < 8; dn++) {
                uint32_t vh2[2], vl2[2];
                uint32_t vaddr = sbase + AS_VHI
                    + (ks * 16 + (lane & 7) + ((lane >> 3) & 1) * 8) * APITCH + dn * 16;
                ldsm_x2_t(vh2, vaddr);
                ldsm_x2_t(vl2, vaddr + (AS_VLO - AS_VHI));
                mma_bf16(o[dn], pah, vh2);
                mma_bf16(o[dn], pal, vh2);
                mma_bf16(o[dn], pah, vl2);
            }
        }
        __syncthreads();
    }

    float lr0 = l0 + __shfl_xor_sync(0xffffffffu, l0, 1);
    lr0 += __shfl_xor_sync(0xffffffffu, lr0, 2);
    float lr1 = l1 + __shfl_xor_sync(0xffffffffu, l1, 1);
    lr1 += __shfl_xor_sync(0xffffffffu, lr1, 2);
    float inv0 = 1.0f / lr0, inv1 = 1.0f / lr1;

    float* O0 = g_attn + ((size_t)b * SS + row0) * DD + h * 64;
    float* O1 = g_attn + ((size_t)b * SS + row1) * DD + h * 64;
#pragma unroll
    for (int dn = 0; dn < 8; dn++) {
        int col = dn * 8 + (lane & 3) * 2;
        *(float2*)&O0[col] = make_float2(o[dn][0] * inv0, o[dn][1] * inv0);
        *(float2*)&O1[col] = make_float2(o[dn][2] * inv1, o[dn][3] * inv1);
    }
}

// ---------------------------------------------------------------------------
// Launch
// ---------------------------------------------------------------------------
extern "C" void kernel_launch(void* const* d_in, const int* in_sizes, int n_in,
                              void* d_out, int out_size) {
    const float* q  = (const float*)d_in[0];
    const float* k  = (const float*)d_in[1];
    const float* v  = (const float*)d_in[2];
    const float* Wq = (const float*)d_in[4];
    const float* bq = (const float*)d_in[5];
    const float* Wk = (const float*)d_in[6];
    const float* bk = (const float*)d_in[7];
    const float* Wv = (const float*)d_in[8];
    const float* bv = (const float*)d_in[9];
    const float* Wo = (const float*)d_in[10];
    const float* bo = (const float*)d_in[11];
    float* out = (float*)d_out;

    float *tmpq, *tmpk, *tmpv, *attn;
    __nv_bfloat16 *whi, *wlo, *ahi, *alo, *qhi, *qlo, *khi, *klo, *vhi, *vlo;
    cudaGetSymbolAddress((void**)&tmpq, g_tmpq);
    cudaGetSymbolAddress((void**)&tmpk, g_tmpk);
    cudaGetSymbolAddress((void**)&tmpv, g_tmpv);
    cudaGetSymbolAddress((void**)&attn, g_attn);
    cudaGetSymbolAddress((void**)&whi,  g_whi);
    cudaGetSymbolAddress((void**)&wlo,  g_wlo);
    cudaGetSymbolAddress((void**)&ahi,  g_ahi);
    cudaGetSymbolAddress((void**)&alo,  g_alo);
    cudaGetSymbolAddress((void**)&qhi,  g_qhi);
    cudaGetSymbolAddress((void**)&qlo,  g_qlo);
    cudaGetSymbolAddress((void**)&khi,  g_khi);
    cudaGetSymbolAddress((void**)&klo,  g_klo);
    cudaGetSymbolAddress((void**)&vhi,  g_vhi);
    cudaGetSymbolAddress((void**)&vlo,  g_vlo);

    cudaFuncSetAttribute(gemm_mma2_kernel, cudaFuncAttributeMaxDynamicSharedMemorySize, GEMM_SMEM);
    cudaFuncSetAttribute(attn_mma_kernel, cudaFuncAttributeMaxDynamicSharedMemorySize, ATTN_SMEM);

    dim3 wgrid(32, 32);
    dim3 wblk(32, 32);
    dim3 ggrid(GN / 128, GM / 128);
    const int NSPLIT = (GM * GK) / 4 / 256;  // blocks for asplit

    // Q/K/V projections
    asplit_kernel<<<NSPLIT, 256>>>((const float4*)q, (uint2*)ahi, (uint2*)alo);
    wsplit_kernel<<<wgrid, wblk>>>(Wq, whi, wlo);
    gemm_mma2_kernel<<<ggrid, 256, GEMM_SMEM>>>(ahi, alo, whi, wlo, bq, tmpq);
    asplit_kernel<<<NSPLIT, 256>>>((const float4*)k, (uint2*)ahi, (uint2*)alo);
    wsplit_kernel<<<wgrid, wblk>>>(Wk, whi, wlo);
    gemm_mma2_kernel<<<ggrid, 256, GEMM_SMEM>>>(ahi, alo, whi, wlo, bk, tmpk);
    asplit_kernel<<<NSPLIT, 256>>>((const float4*)v, (uint2*)ahi, (uint2*)alo);
    wsplit_kernel<<<wgrid, wblk>>>(Wv, whi, wlo);
    gemm_mma2_kernel<<<ggrid, 256, GEMM_SMEM>>>(ahi, alo, whi, wlo, bv, tmpv);

    // RoPE + split to bf16 hi/lo [B,H,S,DK]
    rope_table_kernel<<<SS, 32>>>();
    rope_split_kernel<<<(BB * SS * HH * 32) / 256, 256>>>(tmpq, qhi, qlo);
    rope_split_kernel<<<(BB * SS * HH * 32) / 256, 256>>>(tmpk, khi, klo);
    vsplit_kernel<<<(BB * SS * DD) / 256, 256>>>(tmpv, vhi, vlo);

    // Attention on tensor cores
    attn_mma_kernel<<<dim3(SS / 128, HH, BB), 256, ATTN_SMEM>>>();

    // Output projection
    asplit_kernel<<<NSPLIT, 256>>>((const float4*)attn, (uint2*)ahi, (uint2*)alo);
    wsplit_kernel<<<wgrid, wblk>>>(Wo, whi, wlo);
    gemm_mma2_kernel<<<ggrid, 256, GEMM_SMEM>>>(ahi, alo, whi, wlo, bo, out);
}

// round 7
// speedup vs baseline: 3.1342x; 1.0570x over previous
#include <cuda_runtime.h>
#include <cuda_bf16.h>
#include <cstdint>
#include <math.h>

#define BB 2
#define SS 2048
#define DD 1024
#define HH 16
#define DKK 64

#define GM 4096
#define GN 1024
#define GK 1024
#define PITCH 80

// ---------------------------------------------------------------------------
// Scratch
// ---------------------------------------------------------------------------
__device__ float g_tmpq[BB*SS*DD];
__device__ float g_tmpk[BB*SS*DD];
__device__ float g_tmpv[BB*SS*DD];
__device__ float g_attn[BB*SS*DD];
__device__ float g_cos[SS*32];
__device__ float g_sin[SS*32];
__device__ __nv_bfloat16 g_whi[3*DD*DD];
__device__ __nv_bfloat16 g_wlo[3*DD*DD];
__device__ __nv_bfloat16 g_ahi[3*GM*GK];
__device__ __nv_bfloat16 g_alo[3*GM*GK];
__device__ __nv_bfloat16 g_qhi[BB*SS*DD];
__device__ __nv_bfloat16 g_qlo[BB*SS*DD];
__device__ __nv_bfloat16 g_khi[BB*SS*DD];
__device__ __nv_bfloat16 g_klo[BB*SS*DD];
__device__ __nv_bfloat16 g_vhi[BB*SS*DD];
__device__ __nv_bfloat16 g_vlo[BB*SS*DD];

// ---------------------------------------------------------------------------
// helpers
// ---------------------------------------------------------------------------
__device__ __forceinline__ uint32_t smem_u32(const void* p) {
    uint32_t a;
    asm("{ .reg .u64 t; cvta.to.shared.u64 t, %1; cvt.u32.u64 %0, t; }"
        : "=r"(a) : "l"(p));
    return a;
}
__device__ __forceinline__ void ldsm_x4(uint32_t* r, uint32_t addr) {
    asm volatile("ldmatrix.sync.aligned.m8n8.x4.shared.b16 {%0,%1,%2,%3}, [%4];"
        : "=r"(r[0]), "=r"(r[1]), "=r"(r[2]), "=r"(r[3]) : "r"(addr));
}
__device__ __forceinline__ void ldsm_x2(uint32_t* r, uint32_t addr) {
    asm volatile("ldmatrix.sync.aligned.m8n8.x2.shared.b16 {%0,%1}, [%2];"
        : "=r"(r[0]), "=r"(r[1]) : "r"(addr));
}
__device__ __forceinline__ void ldsm_x2_t(uint32_t* r, uint32_t addr) {
    asm volatile("ldmatrix.sync.aligned.m8n8.x2.trans.shared.b16 {%0,%1}, [%2];"
        : "=r"(r[0]), "=r"(r[1]) : "r"(addr));
}
__device__ __forceinline__ void mma_bf16(float* d, const uint32_t* a, const uint32_t* b) {
    asm volatile(
        "mma.sync.aligned.m16n8k16.row.col.f32.bf16.bf16.f32 "
        "{%0,%1,%2,%3}, {%4,%5,%6,%7}, {%8,%9}, {%0,%1,%2,%3};"
        : "+f"(d[0]), "+f"(d[1]), "+f"(d[2]), "+f"(d[3])
        : "r"(a[0]), "r"(a[1]), "r"(a[2]), "r"(a[3]), "r"(b[0]), "r"(b[1]));
}
__device__ __forceinline__ uint32_t pack2(__nv_bfloat16 lo, __nv_bfloat16 hi) {
    return ((uint32_t)__bfloat16_as_ushort(hi) << 16) | __bfloat16_as_ushort(lo);
}
__device__ __forceinline__ void cp_async16(uint32_t dst, const void* src) {
    asm volatile("cp.async.cg.shared.global [%0], [%1], 16;" :: "r"(dst), "l"(src));
}
__device__ __forceinline__ void cp_commit() { asm volatile("cp.async.commit_group;"); }
__device__ __forceinline__ void cp_wait0() { asm volatile("cp.async.wait_group 0;"); }
__device__ __forceinline__ void cp_wait1() { asm volatile("cp.async.wait_group 1;"); }

// ---------------------------------------------------------------------------
// Weight transpose + split, 3 weights in one launch (z)
// ---------------------------------------------------------------------------
__global__ void wsplit3_kernel(const float* __restrict__ W0,
                               const float* __restrict__ W1,
                               const float* __restrict__ W2) {
    __shared__ float t[32][33];
    int z = blockIdx.z;
    const float* W = (z == 0) ? W0 : (z == 1) ? W1 : W2;
    size_t base = (size_t)z * DD * DD;
    int k0 = blockIdx.y * 32, n0 = blockIdx.x * 32;
    t[threadIdx.y][threadIdx.x] = W[(k0 + threadIdx.y) * DD + n0 + threadIdx.x];
    __syncthreads();
    float w = t[threadIdx.x][threadIdx.y];
    __nv_bfloat16 h = __float2bfloat16(w);
    __nv_bfloat16 l = __float2bfloat16(w - __bfloat162float(h));
    size_t out = base + (size_t)(n0 + threadIdx.y) * DD + k0 + threadIdx.x;
    g_whi[out] = h;
    g_wlo[out] = l;
}

// ---------------------------------------------------------------------------
// Activation split, up to 3 inputs in one launch (y)
// ---------------------------------------------------------------------------
__global__ void asplit3_kernel(const float4* __restrict__ a0,
                               const float4* __restrict__ a1,
                               const float4* __restrict__ a2) {
    int z = blockIdx.y;
    const float4* in = (z == 0) ? a0 : (z == 1) ? a1 : a2;
    int idx = blockIdx.x * blockDim.x + threadIdx.x;
    size_t base = (size_t)z * (GM * GK / 4) + idx;
    float4 a = in[idx];
    __nv_bfloat16 h0 = __float2bfloat16(a.x);
    __nv_bfloat16 h1 = __float2bfloat16(a.y);
    __nv_bfloat16 h2 = __float2bfloat16(a.z);
    __nv_bfloat16 h3 = __float2bfloat16(a.w);
    ((uint2*)g_ahi)[base] = make_uint2(pack2(h0, h1), pack2(h2, h3));
    ((uint2*)g_alo)[base] = make_uint2(
        pack2(__float2bfloat16(a.x - __bfloat162float(h0)),
              __float2bfloat16(a.y - __bfloat162float(h1))),
        pack2(__float2bfloat16(a.z - __bfloat162float(h2)),
              __float2bfloat16(a.w - __bfloat162float(h3))));
}

// ---------------------------------------------------------------------------
// GEMM v3: CTA 128x256, warp tile 64x64, BK=32, cp.async double-buffer.
// grid (GN/256, GM/128, nz). z selects A-slice, W-slice, bias, C.
// ---------------------------------------------------------------------------
#define ST_ALO 10240
#define ST_B   20480
#define ST_BLO 40960
#define STAGE3 61440
#define GEMM_SMEM (2 * STAGE3)

__global__ void __launch_bounds__(256) gemm_mma3_kernel(
    const float* __restrict__ b0, const float* __restrict__ b1,
    const float* __restrict__ b2,
    float* __restrict__ C0, float* __restrict__ C1, float* __restrict__ C2) {
    extern __shared__ char smem[];
    uint32_t sbase = smem_u32(smem);

    int tid = threadIdx.x;
    int lane = tid & 31, w = tid >> 5;
    int wm = w & 1, wn = w >> 1;
    int bm = blockIdx.y * 128, bn = blockIdx.x * 256;
    int z = blockIdx.z;

    const __nv_bfloat16* Ahi = g_ahi + (size_t)z * GM * GK;
    const __nv_bfloat16* Alo = g_alo + (size_t)z * GM * GK;
    const __nv_bfloat16* Bhi = g_whi + (size_t)z * DD * DD;
    const __nv_bfloat16* Blo = g_wlo + (size_t)z * DD * DD;
    const float* bias = (z == 0) ? b0 : (z == 1) ? b1 : b2;
    float* C = (z == 0) ? C0 : (z == 1) ? C1 : C2;

    float acc[4][8][4] = {};

    uint32_t a_row  = wm * 64 + (lane & 15);
    uint32_t a_coff = (lane >> 4) * 16;
    uint32_t b_rl   = wn * 64 + (lane & 7);
    uint32_t b_coff = ((lane >> 3) & 1) * 16;

    auto load_stage = [&](int k0, int stage) {
        uint32_t stb = sbase + stage * STAGE3;
#pragma unroll
        for (int i = 0; i < 12; i++) {
            int idx = tid + i * 256;       // 0..3071
            if (idx < 1024) {              // A: 2 arrays x 128 rows x 4
                int arr = idx >> 9, s = idx & 511;
                int r = s >> 2, c = s & 3;
                const __nv_bfloat16* src =
                    (arr ? Alo : Ahi) + (size_t)(bm + r) * GK + k0 + c * 8;
                cp_async16(stb + arr * ST_ALO + r * PITCH + c * 16, src);
            } else {                       // B: 2 arrays x 256 rows x 4
                int j = idx - 1024;
                int arr = j >> 10, s = j & 1023;
                int r = s >> 2, c = s & 3;
                const __nv_bfloat16* src =
                    (arr ? Blo : Bhi) + (size_t)(bn + r) * GK + k0 + c * 8;
                cp_async16(stb + ST_B + arr * 20480 + r * PITCH + c * 16, src);
            }
        }
        cp_commit();
    };

    load_stage(0, 0);
    int buf = 0;
    const int NC = GK / 32;

    for (int c = 0; c < NC; c++) {
        cp_wait0();
        __syncthreads();
        if (c + 1 < NC) load_stage((c + 1) * 32, buf ^ 1);

        uint32_t stb = sbase + buf * STAGE3;
#pragma unroll
        for (int ks = 0; ks < 2; ks++) {
            uint32_t kb = ks * 32;
            uint32_t ah[4][4], al[4][4], bh[8][2], bl[8][2];
#pragma unroll
            for (int mi = 0; mi < 4; mi++) {
                uint32_t addr = stb + (a_row + mi * 16) * PITCH + kb + a_coff;
                ldsm_x4(ah[mi], addr);
                ldsm_x4(al[mi], addr + ST_ALO);
            }
#pragma unroll
            for (int ni = 0; ni < 8; ni++) {
                uint32_t addr = stb + ST_B + (b_rl + ni * 8) * PITCH + kb + b_coff;
                ldsm_x2(bh[ni], addr);
                ldsm_x2(bl[ni], addr + 20480);
            }
#pragma unroll
            for (int mi = 0; mi < 4; mi++)
#pragma unroll
                for (int ni = 0; ni < 8; ni++) {
                    mma_bf16(acc[mi][ni], ah[mi], bh[ni]);
                    mma_bf16(acc[mi][ni], al[mi], bh[ni]);
                    mma_bf16(acc[mi][ni], ah[mi], bl[ni]);
                }
        }
        buf ^= 1;
    }

    int r0 = bm + wm * 64 + (lane >> 2);
    int c0 = bn + wn * 64 + (lane & 3) * 2;
#pragma unroll
    for (int mi = 0; mi < 4; mi++) {
#pragma unroll
        for (int ni = 0; ni < 8; ni++) {
            int row = r0 + mi * 16;
            int col = c0 + ni * 8;
            float bb0 = bias[col], bb1 = bias[col + 1];
            *(float2*)&C[(size_t)row * GN + col] =
                make_float2(acc[mi][ni][0] + bb0, acc[mi][ni][1] + bb1);
            *(float2*)&C[(size_t)(row + 8) * GN + col] =
                make_float2(acc[mi][ni][2] + bb0, acc[mi][ni][3] + bb1);
        }
    }
}

// ---------------------------------------------------------------------------
// RoPE tables (double range reduction + float trig)
// ---------------------------------------------------------------------------
__global__ void rope_table_kernel() {
    int p = blockIdx.x;
    int i = threadIdx.x;
    double inv = exp(-((double)(2 * i) / 64.0) * log(10000.0));
    float angf = (float)((double)p * inv);
    double a = (double)angf;
    double n = rint(a * 0.15915494309189535);
    float r = (float)(a - n * 6.283185307179586);
    g_cos[p * 32 + i] = cosf(r);
    g_sin[p * 32 + i] = sinf(r);
}

__global__ void rope_split_kernel(const float* __restrict__ in,
                                  __nv_bfloat16* __restrict__ hi,
                                  __nv_bfloat16* __restrict__ lo) {
    int idx = blockIdx.x * blockDim.x + threadIdx.x;
    int d = idx & 31;
    int h = (idx >> 5) & 15;
    int s = (idx >> 9) & 2047;
    int b = idx >> 20;
    const float* src = in + (b * SS + s) * DD + h * 64;
    float x0 = src[d];
    float x1 = src[d + 32];
    float c = g_cos[s * 32 + d];
    float sn = g_sin[s * 32 + d];
    float y0 = x0 * c - x1 * sn;
    float y1 = x1 * c + x0 * sn;
    int base = ((b * HH + h) * SS + s) * DKK;
    __nv_bfloat16 h0 = __float2bfloat16(y0);
    __nv_bfloat16 h1 = __float2bfloat16(y1);
    hi[base + d]      = h0;
    hi[base + d + 32] = h1;
    lo[base + d]      = __float2bfloat16(y0 - __bfloat162float(h0));
    lo[base + d + 32] = __float2bfloat16(y1 - __bfloat162float(h1));
}

__global__ void vsplit_kernel(const float* __restrict__ in,
                              __nv_bfloat16* __restrict__ hi,
                              __nv_bfloat16* __restrict__ lo) {
    int idx = blockIdx.x * blockDim.x + threadIdx.x;
    int c = idx & 63;
    int h = (idx >> 6) & 15;
    int s = (idx >> 10) & 2047;
    int b = idx >> 21;
    float v = in[(b * SS + s) * DD + h * 64 + c];
    int o = ((b * HH + h) * SS + s) * DKK + c;
    __nv_bfloat16 hh = __float2bfloat16(v);
    hi[o] = hh;
    lo[o] = __float2bfloat16(v - __bfloat162float(hh));
}

// ---------------------------------------------------------------------------
// Flash attention, mma.sync, cp.async double-buffered KV
// ---------------------------------------------------------------------------
#define APITCH 144
#define AS_QHI 0
#define AS_QLO 18432
#define AS_KV  36864
#define KVSTG  36864      // 4 arrays * 64*144
#define ATTN_SMEM (36864 + 2 * KVSTG)   // 110592

__global__ void __launch_bounds__(256) attn_mma_kernel() {
    extern __shared__ char smem[];
    uint32_t sbase = smem_u32(smem);
    int tid = threadIdx.x;
    int lane = tid & 31, w = tid >> 5;
    int qt = blockIdx.x, h = blockIdx.y, b = blockIdx.z;

    size_t hb   = (size_t)(b * HH + h) * SS * DKK;
    size_t qoff = hb + (size_t)qt * 128 * DKK;

    auto load_kv = [&](int j0, int stage) {
        size_t kvb = hb + (size_t)j0 * 64 * DKK;
        uint32_t stb = sbase + AS_KV + stage * KVSTG;
#pragma unroll
        for (int i = 0; i < 8; i++) {
            int idx = tid + i * 256;
            int arr = idx >> 9;
            int s2 = idx & 511;
            int r = s2 >> 3, c = s2 & 7;
            const __nv_bfloat16* src = ((arr == 0) ? g_khi :
                                        (arr == 1) ? g_klo :
                                        (arr == 2) ? g_vhi : g_vlo)
                                       + kvb + r * 64 + c * 8;
            cp_async16(stb + arr * 9216 + r * APITCH + c * 16, src);
        }
        cp_commit();
    };

    // Q staging (plain loads, once)
    {
        const uint4* qh4 = (const uint4*)g_qhi + qoff / 8;
        const uint4* ql4 = (const uint4*)g_qlo + qoff / 8;
#pragma unroll
        for (int i = 0; i < 8; i++) {
            int idx = tid + i * 256;
            int arr = idx >> 10;
            int s2 = idx & 1023;
            int r = s2 >> 3, c = s2 & 7;
            uint4 v = (arr ? ql4 : qh4)[r * 8 + c];
            *(uint4*)(smem + (arr ? AS_QLO : AS_QHI) + r * APITCH + c * 16) = v;
        }
    }
    load_kv(0, 0);
    __syncthreads();

    uint32_t qfh[4][4], qfl[4][4];
    {
        uint32_t arow = w * 16 + (lane & 15);
        uint32_t acoff = (lane >> 4) * 16;
#pragma unroll
        for (int ks = 0; ks < 4; ks++) {
            uint32_t addr = sbase + AS_QHI + arow * APITCH + ks * 32 + acoff;
            ldsm_x4(qfh[ks], addr);
            ldsm_x4(qfl[ks], addr + (AS_QLO - AS_QHI));
        }
    }

    float o[8][4] = {};
    float m0 = -1e30f, m1 = -1e30f, l0 = 0.0f, l1 = 0.0f;
    int row0 = qt * 128 + w * 16 + (lane >> 2);
    int row1 = row0 + 8;

    int buf = 0;
    int jmax = 2 * qt + 1;
    for (int j0 = 0; j0 <= jmax; j0++) {
        bool pref = (j0 + 1 <= jmax);
        if (pref) load_kv(j0 + 1, buf ^ 1);
        if (pref) cp_wait1(); else cp_wait0();
        __syncthreads();

        uint32_t kvb_s = sbase + AS_KV + buf * KVSTG;

        float sacc[8][4] = {};
#pragma unroll
        for (int ks = 0; ks < 4; ks++) {
#pragma unroll
            for (int nt = 0; nt < 8; nt++) {
                uint32_t kh2[2], kl2[2];
                uint32_t kaddr = kvb_s + (nt * 8 + (lane & 7)) * APITCH
                               + ks * 32 + ((lane >> 3) & 1) * 16;
                ldsm_x2(kh2, kaddr);
                ldsm_x2(kl2, kaddr + 9216);
                mma_bf16(sacc[nt], qfh[ks], kh2);
                mma_bf16(sacc[nt], qfl[ks], kh2);
                mma_bf16(sacc[nt], qfh[ks], kl2);
            }
        }

        bool domask = (j0 >= 2 * qt);
        int colb = j0 * 64 + (lane & 3) * 2;
        float mx0 = -1e30f, mx1 = -1e30f;
#pragma unroll
        for (int nt = 0; nt < 8; nt++) {
            float s0 = sacc[nt][0] * 0.125f;
            float s1 = sacc[nt][1] * 0.125f;
            float s2 = sacc[nt][2] * 0.125f;
            float s3 = sacc[nt][3] * 0.125f;
            if (domask) {
                int c0 = colb + nt * 8;
                if (c0     > row0) s0 = -1e30f;
                if (c0 + 1 > row0) s1 = -1e30f;
                if (c0     > row1) s2 = -1e30f;
                if (c0 + 1 > row1) s3 = -1e30f;
            }
            sacc[nt][0] = s0; sacc[nt][1] = s1;
            sacc[nt][2] = s2; sacc[nt][3] = s3;
            mx0 = fmaxf(mx0, fmaxf(s0, s1));
            mx1 = fmaxf(mx1, fmaxf(s2, s3));
        }
        mx0 = fmaxf(mx0, __shfl_xor_sync(0xffffffffu, mx0, 1));
        mx0 = fmaxf(mx0, __shfl_xor_sync(0xffffffffu, mx0, 2));
        mx1 = fmaxf(mx1, __shfl_xor_sync(0xffffffffu, mx1, 1));
        mx1 = fmaxf(mx1, __shfl_xor_sync(0xffffffffu, mx1, 2));

        float mn0 = fmaxf(m0, mx0), mn1 = fmaxf(m1, mx1);
        float al0 = __expf(m0 - mn0), al1 = __expf(m1 - mn1);
        m0 = mn0; m1 = mn1;

        uint32_t phi[8][2], plo[8][2];
        float ls0 = 0.0f, ls1 = 0.0f;
#pragma unroll
        for (int nt = 0; nt < 8; nt++) {
            float p0 = __expf(sacc[nt][0] - mn0);
            float p1 = __expf(sacc[nt][1] - mn0);
            float p2 = __expf(sacc[nt][2] - mn1);
            float p3 = __expf(sacc[nt][3] - mn1);
            ls0 += p0 + p1; ls1 += p2 + p3;
            __nv_bfloat16 h0 = __float2bfloat16(p0);
            __nv_bfloat16 h1 = __float2bfloat16(p1);
            __nv_bfloat16 h2 = __float2bfloat16(p2);
            __nv_bfloat16 h3 = __float2bfloat16(p3);
            phi[nt][0] = pack2(h0, h1);
            phi[nt][1] = pack2(h2, h3);
            plo[nt][0] = pack2(__float2bfloat16(p0 - __bfloat162float(h0)),
                               __float2bfloat16(p1 - __bfloat162float(h1)));
            plo[nt][1] = pack2(__float2bfloat16(p2 - __bfloat162float(h2)),
                               __float2bfloat16(p3 - __bfloat162float(h3)));
        }
        l0 = l0 * al0 + ls0;
        l1 = l1 * al1 + ls1;
#pragma unroll
        for (int nt = 0; nt < 8; nt++) {
            o[nt][0] *= al0; o[nt][1] *= al0;
            o[nt][2] *= al1; o[nt][3] *= al1;
        }

#pragma unroll
        for (int ks = 0; ks < 4; ks++) {
            uint32_t pah[4] = {phi[2*ks][0], phi[2*ks][1], phi[2*ks+1][0], phi[2*ks+1][1]};
            uint32_t pal[4] = {plo[2*ks][0], plo[2*ks][1], plo[2*ks+1][0], plo[2*ks+1][1]};
#pragma unroll
            for (int dn = 0; dn < 8; dn++) {
                uint32_t vh2[2], vl2[2];
                uint32_t vaddr = kvb_s + 2 * 9216
                    + (ks * 16 + (lane & 7) + ((lane >> 3) & 1) * 8) * APITCH + dn * 16;
                ldsm_x2_t(vh2, vaddr);
                ldsm_x2_t(vl2, vaddr + 9216);
                mma_bf16(o[dn], pah, vh2);
                mma_bf16(o[dn], pal, vh2);
                mma_bf16(o[dn], pah, vl2);
            }
        }
        __syncthreads();
        buf ^= 1;
    }

    float lr0 = l0 + __shfl_xor_sync(0xffffffffu, l0, 1);
    lr0 += __shfl_xor_sync(0xffffffffu, lr0, 2);
    float lr1 = l1 + __shfl_xor_sync(0xffffffffu, l1, 1);
    lr1 += __shfl_xor_sync(0xffffffffu, lr1, 2);
    float inv0 = 1.0f / lr0, inv1 = 1.0f / lr1;

    float* O0 = g_attn + ((size_t)b * SS + row0) * DD + h * 64;
    float* O1 = g_attn + ((size_t)b * SS + row1) * DD + h * 64;
#pragma unroll
    for (int dn = 0; dn < 8; dn++) {
        int col = dn * 8 + (lane & 3) * 2;
        *(float2*)&O0[col] = make_float2(o[dn][0] * inv0, o[dn][1] * inv0);
        *(float2*)&O1[col] = make_float2(o[dn][2] * inv1, o[dn][3] * inv1);
    }
}

// ---------------------------------------------------------------------------
// Launch
// ---------------------------------------------------------------------------
extern "C" void kernel_launch(void* const* d_in, const int* in_sizes, int n_in,
                              void* d_out, int out_size) {
    const float* q  = (const float*)d_in[0];
    const float* k  = (const float*)d_in[1];
    const float* v  = (const float*)d_in[2];
    const float* Wq = (const float*)d_in[4];
    const float* bq = (const float*)d_in[5];
    const float* Wk = (const float*)d_in[6];
    const float* bk = (const float*)d_in[7];
    const float* Wv = (const float*)d_in[8];
    const float* bv = (const float*)d_in[9];
    const float* Wo = (const float*)d_in[10];
    const float* bo = (const float*)d_in[11];
    float* out = (float*)d_out;

    float *tmpq, *tmpk, *tmpv, *attn;
    __nv_bfloat16 *qhi, *qlo, *khi, *klo, *vhi, *vlo;
    cudaGetSymbolAddress((void**)&tmpq, g_tmpq);
    cudaGetSymbolAddress((void**)&tmpk, g_tmpk);
    cudaGetSymbolAddress((void**)&tmpv, g_tmpv);
    cudaGetSymbolAddress((void**)&attn, g_attn);
    cudaGetSymbolAddress((void**)&qhi,  g_qhi);
    cudaGetSymbolAddress((void**)&qlo,  g_qlo);
    cudaGetSymbolAddress((void**)&khi,  g_khi);
    cudaGetSymbolAddress((void**)&klo,  g_klo);
    cudaGetSymbolAddress((void**)&vhi,  g_vhi);
    cudaGetSymbolAddress((void**)&vlo,  g_vlo);

    cudaFuncSetAttribute(gemm_mma3_kernel, cudaFuncAttributeMaxDynamicSharedMemorySize, GEMM_SMEM);
    cudaFuncSetAttribute(attn_mma_kernel, cudaFuncAttributeMaxDynamicSharedMemorySize, ATTN_SMEM);

    const int NSPLIT = (GM * GK / 4) / 256;   // 4096

    // splits + RoPE tables
    asplit3_kernel<<<dim3(NSPLIT, 3), 256>>>((const float4*)q, (const float4*)k, (const float4*)v);
    wsplit3_kernel<<<dim3(32, 32, 3), dim3(32, 32)>>>(Wq, Wk, Wv);
    rope_table_kernel<<<SS, 32>>>();

    // merged QKV projection
    gemm_mma3_kernel<<<dim3(GN / 256, GM / 128, 3), 256, GEMM_SMEM>>>(
        bq, bk, bv, tmpq, tmpk, tmpv);

    // RoPE + split to [B,H,S,DK]
    rope_split_kernel<<<(BB * SS * HH * 32) / 256, 256>>>(tmpq, qhi, qlo);
    rope_split_kernel<<<(BB * SS * HH * 32) / 256, 256>>>(tmpk, khi, klo);
    vsplit_kernel<<<(BB * SS * DD) / 256, 256>>>(tmpv, vhi, vlo);

    // attention
    attn_mma_kernel<<<dim3(SS / 128, HH, BB), 256, ATTN_SMEM>>>();

    // output projection (z=1 path uses slice 0)
    asplit3_kernel<<<dim3(NSPLIT, 1), 256>>>((const float4*)attn, (const float4*)attn, (const float4*)attn);
    wsplit3_kernel<<<dim3(32, 32, 1), dim3(32, 32)>>>(Wo, Wo, Wo);
    gemm_mma3_kernel<<<dim3(GN / 256, GM / 128, 1), 256, GEMM_SMEM>>>(
        bo, bo, bo, out, out, out);
}

// round 8
// speedup vs baseline: 6.1337x; 1.9571x over previous
#include <cuda_runtime.h>
#include <cuda_fp16.h>
#include <cstdint>
#include <math.h>

#define BB 2
#define SS 2048
#define DD 1024
#define HH 16
#define DKK 64

#define GM 4096
#define GN 1024
#define GK 1024
#define PITCH 80

// ---------------------------------------------------------------------------
// Scratch
// ---------------------------------------------------------------------------
__device__ float g_tmpq[BB*SS*DD];
__device__ float g_tmpk[BB*SS*DD];
__device__ float g_tmpv[BB*SS*DD];
__device__ float g_attn[BB*SS*DD];
__device__ float g_cos[SS*32];
__device__ float g_sin[SS*32];
__device__ __half g_wh[3*DD*DD];   // transposed fp16 weights [N,K]
__device__ __half g_ah[3*GM*GK];   // fp16 activations [M,K]
__device__ __half g_qh2[BB*SS*DD]; // [B,H,S,DK]
__device__ __half g_kh2[BB*SS*DD];
__device__ __half g_vh2[BB*SS*DD];

// ---------------------------------------------------------------------------
// helpers
// ---------------------------------------------------------------------------
__device__ __forceinline__ uint32_t smem_u32(const void* p) {
    uint32_t a;
    asm("{ .reg .u64 t; cvta.to.shared.u64 t, %1; cvt.u32.u64 %0, t; }"
        : "=r"(a) : "l"(p));
    return a;
}
__device__ __forceinline__ void ldsm_x4(uint32_t* r, uint32_t addr) {
    asm volatile("ldmatrix.sync.aligned.m8n8.x4.shared.b16 {%0,%1,%2,%3}, [%4];"
        : "=r"(r[0]), "=r"(r[1]), "=r"(r[2]), "=r"(r[3]) : "r"(addr));
}
__device__ __forceinline__ void ldsm_x2(uint32_t* r, uint32_t addr) {
    asm volatile("ldmatrix.sync.aligned.m8n8.x2.shared.b16 {%0,%1}, [%2];"
        : "=r"(r[0]), "=r"(r[1]) : "r"(addr));
}
__device__ __forceinline__ void ldsm_x2_t(uint32_t* r, uint32_t addr) {
    asm volatile("ldmatrix.sync.aligned.m8n8.x2.trans.shared.b16 {%0,%1}, [%2];"
        : "=r"(r[0]), "=r"(r[1]) : "r"(addr));
}
__device__ __forceinline__ void mma_f16(float* d, const uint32_t* a, const uint32_t* b) {
    asm volatile(
        "mma.sync.aligned.m16n8k16.row.col.f32.f16.f16.f32 "
        "{%0,%1,%2,%3}, {%4,%5,%6,%7}, {%8,%9}, {%0,%1,%2,%3};"
        : "+f"(d[0]), "+f"(d[1]), "+f"(d[2]), "+f"(d[3])
        : "r"(a[0]), "r"(a[1]), "r"(a[2]), "r"(a[3]), "r"(b[0]), "r"(b[1]));
}
__device__ __forceinline__ uint32_t packh2(__half lo, __half hi) {
    return ((uint32_t)__half_as_ushort(hi) << 16) | __half_as_ushort(lo);
}
__device__ __forceinline__ void cp_async16(uint32_t dst, const void* src) {
    asm volatile("cp.async.cg.shared.global [%0], [%1], 16;" :: "r"(dst), "l"(src));
}
__device__ __forceinline__ void cp_commit() { asm volatile("cp.async.commit_group;"); }
__device__ __forceinline__ void cp_wait0() { asm volatile("cp.async.wait_group 0;"); }
__device__ __forceinline__ void cp_wait1() { asm volatile("cp.async.wait_group 1;"); }

// ---------------------------------------------------------------------------
// Weight transpose + fp16 convert, 3 weights per launch
// ---------------------------------------------------------------------------
__global__ void wconv3_kernel(const float* __restrict__ W0,
                              const float* __restrict__ W1,
                              const float* __restrict__ W2) {
    __shared__ float t[32][33];
    int z = blockIdx.z;
    const float* W = (z == 0) ? W0 : (z == 1) ? W1 : W2;
    size_t base = (size_t)z * DD * DD;
    int k0 = blockIdx.y * 32, n0 = blockIdx.x * 32;
    t[threadIdx.y][threadIdx.x] = W[(k0 + threadIdx.y) * DD + n0 + threadIdx.x];
    __syncthreads();
    g_wh[base + (size_t)(n0 + threadIdx.y) * DD + k0 + threadIdx.x] =
        __float2half_rn(t[threadIdx.x][threadIdx.y]);
}

// ---------------------------------------------------------------------------
// Activation fp16 convert, up to 3 inputs per launch
// ---------------------------------------------------------------------------
__global__ void aconv3_kernel(const float4* __restrict__ a0,
                              const float4* __restrict__ a1,
                              const float4* __restrict__ a2) {
    int z = blockIdx.y;
    const float4* in = (z == 0) ? a0 : (z == 1) ? a1 : a2;
    int idx = blockIdx.x * blockDim.x + threadIdx.x;
    float4 a = in[idx];
    ((uint2*)g_ah)[(size_t)z * (GM * GK / 4) + idx] = make_uint2(
        packh2(__float2half_rn(a.x), __float2half_rn(a.y)),
        packh2(__float2half_rn(a.z), __float2half_rn(a.w)));
}

// ---------------------------------------------------------------------------
// GEMM fp16: CTA 128x256, warp tile 64x64, BK=32, cp.async double-buffer.
// grid (GN/256, GM/128, nz)
// ---------------------------------------------------------------------------
#define ST_B   10240
#define STAGEH 30720
#define GEMM_SMEM (2 * STAGEH)

__global__ void __launch_bounds__(256) gemm_f16_kernel(
    const float* __restrict__ b0, const float* __restrict__ b1,
    const float* __restrict__ b2,
    float* __restrict__ C0, float* __restrict__ C1, float* __restrict__ C2) {
    extern __shared__ char smem[];
    uint32_t sbase = smem_u32(smem);

    int tid = threadIdx.x;
    int lane = tid & 31, w = tid >> 5;
    int wm = w & 1, wn = w >> 1;
    int bm = blockIdx.y * 128, bn = blockIdx.x * 256;
    int z = blockIdx.z;

    const __half* Ah = g_ah + (size_t)z * GM * GK;
    const __half* Bh = g_wh + (size_t)z * DD * DD;
    const float* bias = (z == 0) ? b0 : (z == 1) ? b1 : b2;
    float* C = (z == 0) ? C0 : (z == 1) ? C1 : C2;

    float acc[4][8][4] = {};

    uint32_t a_row  = wm * 64 + (lane & 15);
    uint32_t a_coff = (lane >> 4) * 16;
    uint32_t b_rl   = wn * 64 + (lane & 7);
    uint32_t b_coff = ((lane >> 3) & 1) * 16;

    auto load_stage = [&](int k0, int stage) {
        uint32_t stb = sbase + stage * STAGEH;
#pragma unroll
        for (int i = 0; i < 6; i++) {
            int idx = tid + i * 256;       // 0..1535
            if (idx < 512) {               // A: 128 rows x 4 chunks
                int r = idx >> 2, c = idx & 3;
                cp_async16(stb + r * PITCH + c * 16,
                           Ah + (size_t)(bm + r) * GK + k0 + c * 8);
            } else {                       // B: 256 rows x 4 chunks
                int j = idx - 512;
                int r = j >> 2, c = j & 3;
                cp_async16(stb + ST_B + r * PITCH + c * 16,
                           Bh + (size_t)(bn + r) * GK + k0 + c * 8);
            }
        }
        cp_commit();
    };

    load_stage(0, 0);
    int buf = 0;
    const int NC = GK / 32;

    for (int c = 0; c < NC; c++) {
        cp_wait0();
        __syncthreads();
        if (c + 1 < NC) load_stage((c + 1) * 32, buf ^ 1);

        uint32_t stb = sbase + buf * STAGEH;
#pragma unroll
        for (int ks = 0; ks < 2; ks++) {
            uint32_t kb = ks * 32;
            uint32_t ah[4][4], bh[8][2];
#pragma unroll
            for (int mi = 0; mi < 4; mi++)
                ldsm_x4(ah[mi], stb + (a_row + mi * 16) * PITCH + kb + a_coff);
#pragma unroll
            for (int ni = 0; ni < 8; ni++)
                ldsm_x2(bh[ni], stb + ST_B + (b_rl + ni * 8) * PITCH + kb + b_coff);
#pragma unroll
            for (int mi = 0; mi < 4; mi++)
#pragma unroll
                for (int ni = 0; ni < 8; ni++)
                    mma_f16(acc[mi][ni], ah[mi], bh[ni]);
        }
        buf ^= 1;
    }

    int r0 = bm + wm * 64 + (lane >> 2);
    int c0 = bn + wn * 64 + (lane & 3) * 2;
#pragma unroll
    for (int mi = 0; mi < 4; mi++) {
#pragma unroll
        for (int ni = 0; ni < 8; ni++) {
            int row = r0 + mi * 16;
            int col = c0 + ni * 8;
            float bb0 = bias[col], bb1 = bias[col + 1];
            *(float2*)&C[(size_t)row * GN + col] =
                make_float2(acc[mi][ni][0] + bb0, acc[mi][ni][1] + bb1);
            *(float2*)&C[(size_t)(row + 8) * GN + col] =
                make_float2(acc[mi][ni][2] + bb0, acc[mi][ni][3] + bb1);
        }
    }
}

// ---------------------------------------------------------------------------
// RoPE tables
// ---------------------------------------------------------------------------
__global__ void rope_table_kernel() {
    int p = blockIdx.x;
    int i = threadIdx.x;
    double inv = exp(-((double)(2 * i) / 64.0) * log(10000.0));
    float angf = (float)((double)p * inv);
    double a = (double)angf;
    double n = rint(a * 0.15915494309189535);
    float r = (float)(a - n * 6.283185307179586);
    g_cos[p * 32 + i] = cosf(r);
    g_sin[p * 32 + i] = sinf(r);
}

// RoPE + transpose + fp16: z=0 -> Q, z=1 -> K
__global__ void rope_conv_kernel(const float* __restrict__ inq,
                                 const float* __restrict__ ink) {
    int idx = blockIdx.x * blockDim.x + threadIdx.x;
    int z = blockIdx.y;
    const float* in = z ? ink : inq;
    __half* out = z ? g_kh2 : g_qh2;
    int d = idx & 31;
    int h = (idx >> 5) & 15;
    int s = (idx >> 9) & 2047;
    int b = idx >> 20;
    const float* src = in + (b * SS + s) * DD + h * 64;
    float x0 = src[d];
    float x1 = src[d + 32];
    float c = g_cos[s * 32 + d];
    float sn = g_sin[s * 32 + d];
    int base = ((b * HH + h) * SS + s) * DKK;
    out[base + d]      = __float2half_rn(x0 * c - x1 * sn);
    out[base + d + 32] = __float2half_rn(x1 * c + x0 * sn);
}

__global__ void vconv_kernel(const float* __restrict__ in) {
    int idx = blockIdx.x * blockDim.x + threadIdx.x;
    int c = idx & 63;
    int h = (idx >> 6) & 15;
    int s = (idx >> 10) & 2047;
    int b = idx >> 21;
    g_vh2[((b * HH + h) * SS + s) * DKK + c] =
        __float2half_rn(in[(b * SS + s) * DD + h * 64 + c]);
}

// ---------------------------------------------------------------------------
// Flash attention, fp16 mma.sync, cp.async double-buffered KV
// Q tile 128 x KV tile 64, 8 warps x 16 q-rows
// ---------------------------------------------------------------------------
#define APITCH 144
#define AS_Q   0
#define AS_KV  18432               // 128*144
#define KVSTG  18432               // 2 arrays * 64*144
#define ATTN_SMEM (18432 + 2 * KVSTG)   // 55296

__global__ void __launch_bounds__(256) attn_f16_kernel() {
    extern __shared__ char smem[];
    uint32_t sbase = smem_u32(smem);
    int tid = threadIdx.x;
    int lane = tid & 31, w = tid >> 5;
    int qt = blockIdx.x, h = blockIdx.y, b = blockIdx.z;

    size_t hb   = (size_t)(b * HH + h) * SS * DKK;
    size_t qoff = hb + (size_t)qt * 128 * DKK;

    auto load_kv = [&](int j0, int stage) {
        size_t kvb = hb + (size_t)j0 * 64 * DKK;
        uint32_t stb = sbase + AS_KV + stage * KVSTG;
#pragma unroll
        for (int i = 0; i < 4; i++) {
            int idx = tid + i * 256;        // 0..1023
            int arr = idx >> 9;             // 0 K, 1 V
            int s2 = idx & 511;
            int r = s2 >> 3, c = s2 & 7;
            const __half* src = (arr ? g_vh2 : g_kh2) + kvb + r * 64 + c * 8;
            cp_async16(stb + arr * 9216 + r * APITCH + c * 16, src);
        }
        cp_commit();
    };

    // Q staging
    {
        const uint4* q4 = (const uint4*)g_qh2 + qoff / 8;
#pragma unroll
        for (int i = 0; i < 4; i++) {
            int idx = tid + i * 256;        // 0..1023
            int r = idx >> 3, c = idx & 7;
            *(uint4*)(smem + AS_Q + r * APITCH + c * 16) = q4[r * 8 + c];
        }
    }
    load_kv(0, 0);
    __syncthreads();

    uint32_t qf[4][4];
    {
        uint32_t arow = w * 16 + (lane & 15);
        uint32_t acoff = (lane >> 4) * 16;
#pragma unroll
        for (int ks = 0; ks < 4; ks++)
            ldsm_x4(qf[ks], sbase + AS_Q + arow * APITCH + ks * 32 + acoff);
    }

    float o[8][4] = {};
    float m0 = -1e30f, m1 = -1e30f, l0 = 0.0f, l1 = 0.0f;
    int row0 = qt * 128 + w * 16 + (lane >> 2);
    int row1 = row0 + 8;

    int buf = 0;
    int jmax = 2 * qt + 1;
    for (int j0 = 0; j0 <= jmax; j0++) {
        bool pref = (j0 + 1 <= jmax);
        if (pref) load_kv(j0 + 1, buf ^ 1);
        if (pref) cp_wait1(); else cp_wait0();
        __syncthreads();

        uint32_t kvb_s = sbase + AS_KV + buf * KVSTG;

        float sacc[8][4] = {};
#pragma unroll
        for (int ks = 0; ks < 4; ks++) {
#pragma unroll
            for (int nt = 0; nt < 8; nt++) {
                uint32_t k2[2];
                ldsm_x2(k2, kvb_s + (nt * 8 + (lane & 7)) * APITCH
                            + ks * 32 + ((lane >> 3) & 1) * 16);
                mma_f16(sacc[nt], qf[ks], k2);
            }
        }

        bool domask = (j0 >= 2 * qt);
        int colb = j0 * 64 + (lane & 3) * 2;
        float mx0 = -1e30f, mx1 = -1e30f;
#pragma unroll
        for (int nt = 0; nt < 8; nt++) {
            float s0 = sacc[nt][0] * 0.125f;
            float s1 = sacc[nt][1] * 0.125f;
            float s2 = sacc[nt][2] * 0.125f;
            float s3 = sacc[nt][3] * 0.125f;
            if (domask) {
                int c0 = colb + nt * 8;
                if (c0     > row0) s0 = -1e30f;
                if (c0 + 1 > row0) s1 = -1e30f;
                if (c0     > row1) s2 = -1e30f;
                if (c0 + 1 > row1) s3 = -1e30f;
            }
            sacc[nt][0] = s0; sacc[nt][1] = s1;
            sacc[nt][2] = s2; sacc[nt][3] = s3;
            mx0 = fmaxf(mx0, fmaxf(s0, s1));
            mx1 = fmaxf(mx1, fmaxf(s2, s3));
        }
        mx0 = fmaxf(mx0, __shfl_xor_sync(0xffffffffu, mx0, 1));
        mx0 = fmaxf(mx0, __shfl_xor_sync(0xffffffffu, mx0, 2));
        mx1 = fmaxf(mx1, __shfl_xor_sync(0xffffffffu, mx1, 1));
        mx1 = fmaxf(mx1, __shfl_xor_sync(0xffffffffu, mx1, 2));

        float mn0 = fmaxf(m0, mx0), mn1 = fmaxf(m1, mx1);
        float al0 = __expf(m0 - mn0), al1 = __expf(m1 - mn1);
        m0 = mn0; m1 = mn1;

        uint32_t pf[8][2];
        float ls0 = 0.0f, ls1 = 0.0f;
#pragma unroll
        for (int nt = 0; nt < 8; nt++) {
            float p0 = __expf(sacc[nt][0] - mn0);
            float p1 = __expf(sacc[nt][1] - mn0);
            float p2 = __expf(sacc[nt][2] - mn1);
            float p3 = __expf(sacc[nt][3] - mn1);
            ls0 += p0 + p1; ls1 += p2 + p3;
            pf[nt][0] = packh2(__float2half_rn(p0), __float2half_rn(p1));
            pf[nt][1] = packh2(__float2half_rn(p2), __float2half_rn(p3));
        }
        l0 = l0 * al0 + ls0;
        l1 = l1 * al1 + ls1;
#pragma unroll
        for (int nt = 0; nt < 8; nt++) {
            o[nt][0] *= al0; o[nt][1] *= al0;
            o[nt][2] *= al1; o[nt][3] *= al1;
        }

#pragma unroll
        for (int ks = 0; ks < 4; ks++) {
            uint32_t pa[4] = {pf[2*ks][0], pf[2*ks][1], pf[2*ks+1][0], pf[2*ks+1][1]};
#pragma unroll
            for (int dn = 0; dn < 8; dn++) {
                uint32_t v2[2];
                ldsm_x2_t(v2, kvb_s + 9216
                    + (ks * 16 + (lane & 7) + ((lane >> 3) & 1) * 8) * APITCH + dn * 16);
                mma_f16(o[dn], pa, v2);
            }
        }
        __syncthreads();
        buf ^= 1;
    }

    float lr0 = l0 + __shfl_xor_sync(0xffffffffu, l0, 1);
    lr0 += __shfl_xor_sync(0xffffffffu, lr0, 2);
    float lr1 = l1 + __shfl_xor_sync(0xffffffffu, l1, 1);
    lr1 += __shfl_xor_sync(0xffffffffu, lr1, 2);
    float inv0 = 1.0f / lr0, inv1 = 1.0f / lr1;

    float* O0 = g_attn + ((size_t)b * SS + row0) * DD + h * 64;
    float* O1 = g_attn + ((size_t)b * SS + row1) * DD + h * 64;
#pragma unroll
    for (int dn = 0; dn < 8; dn++) {
        int col = dn * 8 + (lane & 3) * 2;
        *(float2*)&O0[col] = make_float2(o[dn][0] * inv0, o[dn][1] * inv0);
        *(float2*)&O1[col] = make_float2(o[dn][2] * inv1, o[dn][3] * inv1);
    }
}

// ---------------------------------------------------------------------------
// Launch
// ---------------------------------------------------------------------------
extern "C" void kernel_launch(void* const* d_in, const int* in_sizes, int n_in,
                              void* d_out, int out_size) {
    const float* q  = (const float*)d_in[0];
    const float* k  = (const float*)d_in[1];
    const float* v  = (const float*)d_in[2];
    const float* Wq = (const float*)d_in[4];
    const float* bq = (const float*)d_in[5];
    const float* Wk = (const float*)d_in[6];
    const float* bk = (const float*)d_in[7];
    const float* Wv = (const float*)d_in[8];
    const float* bv = (const float*)d_in[9];
    const float* Wo = (const float*)d_in[10];
    const float* bo = (const float*)d_in[11];
    float* out = (float*)d_out;

    float *tmpq, *tmpk, *tmpv, *attn;
    cudaGetSymbolAddress((void**)&tmpq, g_tmpq);
    cudaGetSymbolAddress((void**)&tmpk, g_tmpk);
    cudaGetSymbolAddress((void**)&tmpv, g_tmpv);
    cudaGetSymbolAddress((void**)&attn, g_attn);

    cudaFuncSetAttribute(gemm_f16_kernel, cudaFuncAttributeMaxDynamicSharedMemorySize, GEMM_SMEM);
    cudaFuncSetAttribute(attn_f16_kernel, cudaFuncAttributeMaxDynamicSharedMemorySize, ATTN_SMEM);

    const int NCONV = (GM * GK / 4) / 256;   // 4096

    aconv3_kernel<<<dim3(NCONV, 3), 256>>>((const float4*)q, (const float4*)k, (const float4*)v);
    wconv3_kernel<<<dim3(32, 32, 3), dim3(32, 32)>>>(Wq, Wk, Wv);
    rope_table_kernel<<<SS, 32>>>();

    gemm_f16_kernel<<<dim3(GN / 256, GM / 128, 3), 256, GEMM_SMEM>>>(
        bq, bk, bv, tmpq, tmpk, tmpv);

    rope_conv_kernel<<<dim3((BB * SS * HH * 32) / 256, 2), 256>>>(tmpq, tmpk);
    vconv_kernel<<<(BB * SS * DD) / 256, 256>>>(tmpv);

    attn_f16_kernel<<<dim3(SS / 128, HH, BB), 256, ATTN_SMEM>>>();

    aconv3_kernel<<<dim3(NCONV, 1), 256>>>((const float4*)attn, (const float4*)attn, (const float4*)attn);
    wconv3_kernel<<<dim3(32, 32, 1), dim3(32, 32)>>>(Wo, Wo, Wo);
    gemm_f16_kernel<<<dim3(GN / 256, GM / 128, 1), 256, GEMM_SMEM>>>(
        bo, bo, bo, out, out, out);
}

// round 9
// speedup vs baseline: 6.5010x; 1.0599x over previous
#include <cuda_runtime.h>
#include <cuda_fp16.h>
#include <cstdint>
#include <math.h>

#define BB 2
#define SS 2048
#define DD 1024
#define HH 16
#define DKK 64

#define GM 4096
#define GN 1024
#define GK 1024
#define PITCH 80

// ---------------------------------------------------------------------------
// Scratch
// ---------------------------------------------------------------------------
__device__ float g_cos[SS*32];
__device__ float g_sin[SS*32];
__device__ __half g_wh[4*DD*DD];   // fp16 weights [N,K]: Wq,Wk,Wv,Wo
__device__ __half g_ah[3*GM*GK];   // fp16 activations; slot0 reused for attn out
__device__ __half g_qh2[BB*SS*DD]; // [B,H,S,DK]
__device__ __half g_kh2[BB*SS*DD];
__device__ __half g_vh2[BB*SS*DD];

// ---------------------------------------------------------------------------
// helpers
// ---------------------------------------------------------------------------
__device__ __forceinline__ uint32_t smem_u32(const void* p) {
    uint32_t a;
    asm("{ .reg .u64 t; cvta.to.shared.u64 t, %1; cvt.u32.u64 %0, t; }"
        : "=r"(a) : "l"(p));
    return a;
}
__device__ __forceinline__ void ldsm_x4(uint32_t* r, uint32_t addr) {
    asm volatile("ldmatrix.sync.aligned.m8n8.x4.shared.b16 {%0,%1,%2,%3}, [%4];"
        : "=r"(r[0]), "=r"(r[1]), "=r"(r[2]), "=r"(r[3]) : "r"(addr));
}
__device__ __forceinline__ void ldsm_x2(uint32_t* r, uint32_t addr) {
    asm volatile("ldmatrix.sync.aligned.m8n8.x2.shared.b16 {%0,%1}, [%2];"
        : "=r"(r[0]), "=r"(r[1]) : "r"(addr));
}
__device__ __forceinline__ void ldsm_x2_t(uint32_t* r, uint32_t addr) {
    asm volatile("ldmatrix.sync.aligned.m8n8.x2.trans.shared.b16 {%0,%1}, [%2];"
        : "=r"(r[0]), "=r"(r[1]) : "r"(addr));
}
__device__ __forceinline__ void mma_f16(float* d, const uint32_t* a, const uint32_t* b) {
    asm volatile(
        "mma.sync.aligned.m16n8k16.row.col.f32.f16.f16.f32 "
        "{%0,%1,%2,%3}, {%4,%5,%6,%7}, {%8,%9}, {%0,%1,%2,%3};"
        : "+f"(d[0]), "+f"(d[1]), "+f"(d[2]), "+f"(d[3])
        : "r"(a[0]), "r"(a[1]), "r"(a[2]), "r"(a[3]), "r"(b[0]), "r"(b[1]));
}
__device__ __forceinline__ uint32_t packh2(__half lo, __half hi) {
    return ((uint32_t)__half_as_ushort(hi) << 16) | __half_as_ushort(lo);
}
__device__ __forceinline__ void cp_async16(uint32_t dst, const void* src) {
    asm volatile("cp.async.cg.shared.global [%0], [%1], 16;" :: "r"(dst), "l"(src));
}
__device__ __forceinline__ void cp_commit() { asm volatile("cp.async.commit_group;"); }
__device__ __forceinline__ void cp_wait0() { asm volatile("cp.async.wait_group 0;"); }
__device__ __forceinline__ void cp_wait1() { asm volatile("cp.async.wait_group 1;"); }

// ---------------------------------------------------------------------------
// Weight transpose + fp16 convert, 4 weights per launch
// ---------------------------------------------------------------------------
__global__ void wconv4_kernel(const float* __restrict__ W0,
                              const float* __restrict__ W1,
                              const float* __restrict__ W2,
                              const float* __restrict__ W3) {
    __shared__ float t[32][33];
    int z = blockIdx.z;
    const float* W = (z == 0) ? W0 : (z == 1) ? W1 : (z == 2) ? W2 : W3;
    size_t base = (size_t)z * DD * DD;
    int k0 = blockIdx.y * 32, n0 = blockIdx.x * 32;
    t[threadIdx.y][threadIdx.x] = W[(k0 + threadIdx.y) * DD + n0 + threadIdx.x];
    __syncthreads();
    g_wh[base + (size_t)(n0 + threadIdx.y) * DD + k0 + threadIdx.x] =
        __float2half_rn(t[threadIdx.x][threadIdx.y]);
}

// ---------------------------------------------------------------------------
// Activation fp16 convert, 3 inputs per launch
// ---------------------------------------------------------------------------
__global__ void aconv3_kernel(const float4* __restrict__ a0,
                              const float4* __restrict__ a1,
                              const float4* __restrict__ a2) {
    int z = blockIdx.y;
    const float4* in = (z == 0) ? a0 : (z == 1) ? a1 : a2;
    int idx = blockIdx.x * blockDim.x + threadIdx.x;
    float4 a = in[idx];
    ((uint2*)g_ah)[(size_t)z * (GM * GK / 4) + idx] = make_uint2(
        packh2(__float2half_rn(a.x), __float2half_rn(a.y)),
        packh2(__float2half_rn(a.z), __float2half_rn(a.w)));
}

// ---------------------------------------------------------------------------
// RoPE tables
// ---------------------------------------------------------------------------
__global__ void rope_table_kernel() {
    int idx = blockIdx.x * blockDim.x + threadIdx.x;
    int p = idx >> 5, i = idx & 31;
    double inv = exp(-((double)(2 * i) / 64.0) * log(10000.0));
    float angf = (float)((double)p * inv);
    double a = (double)angf;
    double n = rint(a * 0.15915494309189535);
    float r = (float)(a - n * 6.283185307179586);
    g_cos[p * 32 + i] = cosf(r);
    g_sin[p * 32 + i] = sinf(r);
}

// ---------------------------------------------------------------------------
// GEMM fp16: CTA 128x256, warp 64x64, BK=32, 3-stage cp.async.
// mode 1: fused epilogue (bias + RoPE for z<2) -> fp16 [B,H,S,DK]
// mode 0: f32 epilogue with bias -> C   (A slot 0, W slot 3)
// ---------------------------------------------------------------------------
#define ST_B   10240
#define STAGEH 30720
#define GEMM_SMEM (3 * STAGEH)

__global__ void __launch_bounds__(256) gemm_f16_kernel(
    int mode,
    const float* __restrict__ bq, const float* __restrict__ bk,
    const float* __restrict__ bv,
    float* __restrict__ C) {
    extern __shared__ char smem[];
    uint32_t sbase = smem_u32(smem);

    int tid = threadIdx.x;
    int lane = tid & 31, w = tid >> 5;
    int wm = w & 1, wn = w >> 1;
    int bm = blockIdx.y * 128, bn = blockIdx.x * 256;
    int z = blockIdx.z;
    int aslot = mode ? z : 0;
    int wslot = mode ? z : 3;

    const __half* Ah = g_ah + (size_t)aslot * GM * GK;
    const __half* Bh = g_wh + (size_t)wslot * DD * DD;

    float acc[4][8][4] = {};

    uint32_t a_row  = wm * 64 + (lane & 15);
    uint32_t a_coff = (lane >> 4) * 16;
    uint32_t b_rl   = wn * 64 + (lane & 7);
    uint32_t b_coff = ((lane >> 3) & 1) * 16;

    auto load_stage = [&](int k0, int stage) {
        uint32_t stb = sbase + stage * STAGEH;
#pragma unroll
        for (int i = 0; i < 6; i++) {
            int idx = tid + i * 256;
            if (idx < 512) {
                int r = idx >> 2, c = idx & 3;
                cp_async16(stb + r * PITCH + c * 16,
                           Ah + (size_t)(bm + r) * GK + k0 + c * 8);
            } else {
                int j = idx - 512;
                int r = j >> 2, c = j & 3;
                cp_async16(stb + ST_B + r * PITCH + c * 16,
                           Bh + (size_t)(bn + r) * GK + k0 + c * 8);
            }
        }
        cp_commit();
    };

    const int NC = GK / 32;
    load_stage(0, 0);
    load_stage(32, 1);

    for (int c = 0; c < NC; c++) {
        if (c < NC - 1) cp_wait1(); else cp_wait0();
        __syncthreads();
        if (c + 2 < NC) load_stage((c + 2) * 32, (c + 2) % 3);

        uint32_t stb = sbase + (c % 3) * STAGEH;
#pragma unroll
        for (int ks = 0; ks < 2; ks++) {
            uint32_t kb = ks * 32;
            uint32_t ah[4][4], bh[8][2];
#pragma unroll
            for (int mi = 0; mi < 4; mi++)
                ldsm_x4(ah[mi], stb + (a_row + mi * 16) * PITCH + kb + a_coff);
#pragma unroll
            for (int ni = 0; ni < 8; ni++)
                ldsm_x2(bh[ni], stb + ST_B + (b_rl + ni * 8) * PITCH + kb + b_coff);
#pragma unroll
            for (int mi = 0; mi < 4; mi++)
#pragma unroll
                for (int ni = 0; ni < 8; ni++)
                    mma_f16(acc[mi][ni], ah[mi], bh[ni]);
        }
    }

    int r0 = bm + wm * 64 + (lane >> 2);
    int c0 = bn + wn * 64 + (lane & 3) * 2;

    if (mode == 0) {
        const float* bias = bq;   // caller passes bo here
#pragma unroll
        for (int mi = 0; mi < 4; mi++) {
#pragma unroll
            for (int ni = 0; ni < 8; ni++) {
                int row = r0 + mi * 16;
                int col = c0 + ni * 8;
                float bb0 = bias[col], bb1 = bias[col + 1];
                *(float2*)&C[(size_t)row * GN + col] =
                    make_float2(acc[mi][ni][0] + bb0, acc[mi][ni][1] + bb1);
                *(float2*)&C[(size_t)(row + 8) * GN + col] =
                    make_float2(acc[mi][ni][2] + bb0, acc[mi][ni][3] + bb1);
            }
        }
        return;
    }

    // fused epilogue: bias + (RoPE for z<2) -> fp16 [B,H,S,DK]
    const float* bias = (z == 0) ? bq : (z == 1) ? bk : bv;
    __half* outh = (z == 0) ? g_qh2 : (z == 1) ? g_kh2 : g_vh2;
    int hh = (bn >> 6) + wn;

    if (z == 2) {
#pragma unroll
        for (int mi = 0; mi < 4; mi++) {
#pragma unroll
            for (int hf = 0; hf < 2; hf++) {
                int row = r0 + mi * 16 + hf * 8;
                int s = row & (SS - 1), bb = row >> 11;
                size_t base = ((size_t)(bb * HH + hh) * SS + s) * 64;
#pragma unroll
                for (int ni = 0; ni < 8; ni++) {
                    int d = (lane & 3) * 2 + ni * 8;
                    int cn = c0 + ni * 8;
                    *(__half2*)&outh[base + d] = __floats2half2_rn(
                        acc[mi][ni][2 * hf]     + bias[cn],
                        acc[mi][ni][2 * hf + 1] + bias[cn + 1]);
                }
            }
        }
    } else {
#pragma unroll
        for (int mi = 0; mi < 4; mi++) {
#pragma unroll
            for (int hf = 0; hf < 2; hf++) {
                int row = r0 + mi * 16 + hf * 8;
                int s = row & (SS - 1), bb = row >> 11;
                size_t base = ((size_t)(bb * HH + hh) * SS + s) * 64;
#pragma unroll
                for (int ni = 0; ni < 4; ni++) {
                    int d = (lane & 3) * 2 + ni * 8;
                    int cn = c0 + ni * 8;
                    float x0a = acc[mi][ni][2 * hf]       + bias[cn];
                    float x0b = acc[mi][ni][2 * hf + 1]   + bias[cn + 1];
                    float x1a = acc[mi][ni + 4][2 * hf]     + bias[cn + 32];
                    float x1b = acc[mi][ni + 4][2 * hf + 1] + bias[cn + 33];
                    float cA = g_cos[s * 32 + d],  cB = g_cos[s * 32 + d + 1];
                    float sA = g_sin[s * 32 + d],  sB = g_sin[s * 32 + d + 1];
                    *(__half2*)&outh[base + d] = __floats2half2_rn(
                        x0a * cA - x1a * sA, x0b * cB - x1b * sB);
                    *(__half2*)&outh[base + d + 32] = __floats2half2_rn(
                        x1a * cA + x0a * sA, x1b * cB + x0b * sB);
                }
            }
        }
    }
}

// ---------------------------------------------------------------------------
// Flash attention, fp16 mma.sync, 3-stage cp.async KV pipeline
// Q tile 128 x KV tile 64, 8 warps x 16 q-rows; writes fp16 to g_ah slot 0
// ---------------------------------------------------------------------------
#define APITCH 144
#define AS_Q   0
#define AS_KV  18432
#define KVSTG  18432
#define ATTN_SMEM (18432 + 3 * KVSTG)   // 73728

__global__ void __launch_bounds__(256) attn_f16_kernel() {
    extern __shared__ char smem[];
    uint32_t sbase = smem_u32(smem);
    int tid = threadIdx.x;
    int lane = tid & 31, w = tid >> 5;
    int qt = blockIdx.x, h = blockIdx.y, b = blockIdx.z;

    size_t hb   = (size_t)(b * HH + h) * SS * DKK;
    size_t qoff = hb + (size_t)qt * 128 * DKK;

    auto load_kv = [&](int j0, int stage) {
        size_t kvb = hb + (size_t)j0 * 64 * DKK;
        uint32_t stb = sbase + AS_KV + stage * KVSTG;
#pragma unroll
        for (int i = 0; i < 4; i++) {
            int idx = tid + i * 256;
            int arr = idx >> 9;
            int s2 = idx & 511;
            int r = s2 >> 3, c = s2 & 7;
            const __half* src = (arr ? g_vh2 : g_kh2) + kvb + r * 64 + c * 8;
            cp_async16(stb + arr * 9216 + r * APITCH + c * 16, src);
        }
        cp_commit();
    };

    // Q staging
    {
        const uint4* q4 = (const uint4*)g_qh2 + qoff / 8;
#pragma unroll
        for (int i = 0; i < 4; i++) {
            int idx = tid + i * 256;
            int r = idx >> 3, c = idx & 7;
            *(uint4*)(smem + AS_Q + r * APITCH + c * 16) = q4[r * 8 + c];
        }
    }
    int jmax = 2 * qt + 1;
    load_kv(0, 0);
    load_kv(1, 1);
    __syncthreads();

    uint32_t qf[4][4];
    {
        uint32_t arow = w * 16 + (lane & 15);
        uint32_t acoff = (lane >> 4) * 16;
#pragma unroll
        for (int ks = 0; ks < 4; ks++)
            ldsm_x4(qf[ks], sbase + AS_Q + arow * APITCH + ks * 32 + acoff);
    }

    float o[8][4] = {};
    float m0 = -1e30f, m1 = -1e30f, l0 = 0.0f, l1 = 0.0f;
    int row0 = qt * 128 + w * 16 + (lane >> 2);
    int row1 = row0 + 8;

    for (int j0 = 0; j0 <= jmax; j0++) {
        if (j0 < jmax) cp_wait1(); else cp_wait0();
        __syncthreads();
        if (j0 + 2 <= jmax) load_kv(j0 + 2, (j0 + 2) % 3);

        uint32_t kvb_s = sbase + AS_KV + (j0 % 3) * KVSTG;

        float sacc[8][4] = {};
#pragma unroll
        for (int ks = 0; ks < 4; ks++) {
#pragma unroll
            for (int nt = 0; nt < 8; nt++) {
                uint32_t k2[2];
                ldsm_x2(k2, kvb_s + (nt * 8 + (lane & 7)) * APITCH
                            + ks * 32 + ((lane >> 3) & 1) * 16);
                mma_f16(sacc[nt], qf[ks], k2);
            }
        }

        bool domask = (j0 >= 2 * qt);
        int colb = j0 * 64 + (lane & 3) * 2;
        float mx0 = -1e30f, mx1 = -1e30f;
#pragma unroll
        for (int nt = 0; nt < 8; nt++) {
            float s0 = sacc[nt][0] * 0.125f;
            float s1 = sacc[nt][1] * 0.125f;
            float s2 = sacc[nt][2] * 0.125f;
            float s3 = sacc[nt][3] * 0.125f;
            if (domask) {
                int c0 = colb + nt * 8;
                if (c0     > row0) s0 = -1e30f;
                if (c0 + 1 > row0) s1 = -1e30f;
                if (c0     > row1) s2 = -1e30f;
                if (c0 + 1 > row1) s3 = -1e30f;
            }
            sacc[nt][0] = s0; sacc[nt][1] = s1;
            sacc[nt][2] = s2; sacc[nt][3] = s3;
            mx0 = fmaxf(mx0, fmaxf(s0, s1));
            mx1 = fmaxf(mx1, fmaxf(s2, s3));
        }
        mx0 = fmaxf(mx0, __shfl_xor_sync(0xffffffffu, mx0, 1));
        mx0 = fmaxf(mx0, __shfl_xor_sync(0xffffffffu, mx0, 2));
        mx1 = fmaxf(mx1, __shfl_xor_sync(0xffffffffu, mx1, 1));
        mx1 = fmaxf(mx1, __shfl_xor_sync(0xffffffffu, mx1, 2));

        float mn0 = fmaxf(m0, mx0), mn1 = fmaxf(m1, mx1);
        float al0 = __expf(m0 - mn0), al1 = __expf(m1 - mn1);
        m0 = mn0; m1 = mn1;

        uint32_t pf[8][2];
        float ls0 = 0.0f, ls1 = 0.0f;
#pragma unroll
        for (int nt = 0; nt < 8; nt++) {
            float p0 = __expf(sacc[nt][0] - mn0);
            float p1 = __expf(sacc[nt][1] - mn0);
            float p2 = __expf(sacc[nt][2] - mn1);
            float p3 = __expf(sacc[nt][3] - mn1);
            ls0 += p0 + p1; ls1 += p2 + p3;
            pf[nt][0] = packh2(__float2half_rn(p0), __float2half_rn(p1));
            pf[nt][1] = packh2(__float2half_rn(p2), __float2half_rn(p3));
        }
        l0 = l0 * al0 + ls0;
        l1 = l1 * al1 + ls1;
#pragma unroll
        for (int nt = 0; nt < 8; nt++) {
            o[nt][0] *= al0; o[nt][1] *= al0;
            o[nt][2] *= al1; o[nt][3] *= al1;
        }

#pragma unroll
        for (int ks = 0; ks < 4; ks++) {
            uint32_t pa[4] = {pf[2*ks][0], pf[2*ks][1], pf[2*ks+1][0], pf[2*ks+1][1]};
#pragma unroll
            for (int dn = 0; dn < 8; dn++) {
                uint32_t v2[2];
                ldsm_x2_t(v2, kvb_s + 9216
                    + (ks * 16 + (lane & 7) + ((lane >> 3) & 1) * 8) * APITCH + dn * 16);
                mma_f16(o[dn], pa, v2);
            }
        }
    }

    float lr0 = l0 + __shfl_xor_sync(0xffffffffu, l0, 1);
    lr0 += __shfl_xor_sync(0xffffffffu, lr0, 2);
    float lr1 = l1 + __shfl_xor_sync(0xffffffffu, l1, 1);
    lr1 += __shfl_xor_sync(0xffffffffu, lr1, 2);
    float inv0 = 1.0f / lr0, inv1 = 1.0f / lr1;

    // write fp16 directly to O-proj A buffer (g_ah slot 0), [B*S, D] layout
    __half* O0 = g_ah + ((size_t)b * SS + row0) * DD + h * 64;
    __half* O1 = g_ah + ((size_t)b * SS + row1) * DD + h * 64;
#pragma unroll
    for (int dn = 0; dn < 8; dn++) {
        int col = dn * 8 + (lane & 3) * 2;
        *(__half2*)&O0[col] = __floats2half2_rn(o[dn][0] * inv0, o[dn][1] * inv0);
        *(__half2*)&O1[col] = __floats2half2_rn(o[dn][2] * inv1, o[dn][3] * inv1);
    }
}

// ---------------------------------------------------------------------------
// Launch
// ---------------------------------------------------------------------------
extern "C" void kernel_launch(void* const* d_in, const int* in_sizes, int n_in,
                              void* d_out, int out_size) {
    const float* q  = (const float*)d_in[0];
    const float* k  = (const float*)d_in[1];
    const float* v  = (const float*)d_in[2];
    const float* Wq = (const float*)d_in[4];
    const float* bq = (const float*)d_in[5];
    const float* Wk = (const float*)d_in[6];
    const float* bk = (const float*)d_in[7];
    const float* Wv = (const float*)d_in[8];
    const float* bv = (const float*)d_in[9];
    const float* Wo = (const float*)d_in[10];
    const float* bo = (const float*)d_in[11];
    float* out = (float*)d_out;

    cudaFuncSetAttribute(gemm_f16_kernel, cudaFuncAttributeMaxDynamicSharedMemorySize, GEMM_SMEM);
    cudaFuncSetAttribute(attn_f16_kernel, cudaFuncAttributeMaxDynamicSharedMemorySize, ATTN_SMEM);

    const int NCONV = (GM * GK / 4) / 256;   // 4096

    aconv3_kernel<<<dim3(NCONV, 3), 256>>>((const float4*)q, (const float4*)k, (const float4*)v);
    wconv4_kernel<<<dim3(32, 32, 4), dim3(32, 32)>>>(Wq, Wk, Wv, Wo);
    rope_table_kernel<<<256, 256>>>();

    // QKV projection, fused bias+RoPE+fp16 epilogue
    gemm_f16_kernel<<<dim3(GN / 256, GM / 128, 3), 256, GEMM_SMEM>>>(
        1, bq, bk, bv, nullptr);

    // attention (writes fp16 to g_ah slot 0)
    attn_f16_kernel<<<dim3(SS / 128, HH, BB), 256, ATTN_SMEM>>>();

    // output projection
    gemm_f16_kernel<<<dim3(GN / 256, GM / 128, 1), 256, GEMM_SMEM>>>(
        0, bo, nullptr, nullptr, out);
}

// round 10
// speedup vs baseline: 6.8672x; 1.0563x over previous
#include <cuda_runtime.h>
#include <cuda_fp16.h>
#include <cstdint>
#include <math.h>

#define BB 2
#define SS 2048
#define DD 1024
#define HH 16
#define DKK 64

#define GM 4096
#define GN 1024
#define GK 1024
#define PITCH 80

// ---------------------------------------------------------------------------
// Scratch
// ---------------------------------------------------------------------------
__device__ float g_cos[SS*32];
__device__ float g_sin[SS*32];
__device__ __half g_wh[4*DD*DD];   // fp16 weights [N,K]: Wq,Wk,Wv,Wo
__device__ __half g_ah[3*GM*GK];   // fp16 activations; slot0 reused for attn out
__device__ __half g_qh2[BB*SS*DD]; // [B,H,S,DK]
__device__ __half g_kh2[BB*SS*DD];
__device__ __half g_vh2[BB*SS*DD];

// ---------------------------------------------------------------------------
// helpers
// ---------------------------------------------------------------------------
__device__ __forceinline__ uint32_t smem_u32(const void* p) {
    uint32_t a;
    asm("{ .reg .u64 t; cvta.to.shared.u64 t, %1; cvt.u32.u64 %0, t; }"
        : "=r"(a) : "l"(p));
    return a;
}
__device__ __forceinline__ void ldsm_x4(uint32_t* r, uint32_t addr) {
    asm volatile("ldmatrix.sync.aligned.m8n8.x4.shared.b16 {%0,%1,%2,%3}, [%4];"
        : "=r"(r[0]), "=r"(r[1]), "=r"(r[2]), "=r"(r[3]) : "r"(addr));
}
__device__ __forceinline__ void ldsm_x2(uint32_t* r, uint32_t addr) {
    asm volatile("ldmatrix.sync.aligned.m8n8.x2.shared.b16 {%0,%1}, [%2];"
        : "=r"(r[0]), "=r"(r[1]) : "r"(addr));
}
__device__ __forceinline__ void ldsm_x2_t(uint32_t* r, uint32_t addr) {
    asm volatile("ldmatrix.sync.aligned.m8n8.x2.trans.shared.b16 {%0,%1}, [%2];"
        : "=r"(r[0]), "=r"(r[1]) : "r"(addr));
}
__device__ __forceinline__ void mma_f16(float* d, const uint32_t* a, const uint32_t* b) {
    asm volatile(
        "mma.sync.aligned.m16n8k16.row.col.f32.f16.f16.f32 "
        "{%0,%1,%2,%3}, {%4,%5,%6,%7}, {%8,%9}, {%0,%1,%2,%3};"
        : "+f"(d[0]), "+f"(d[1]), "+f"(d[2]), "+f"(d[3])
        : "r"(a[0]), "r"(a[1]), "r"(a[2]), "r"(a[3]), "r"(b[0]), "r"(b[1]));
}
__device__ __forceinline__ uint32_t packh2(__half lo, __half hi) {
    return ((uint32_t)__half_as_ushort(hi) << 16) | __half_as_ushort(lo);
}
__device__ __forceinline__ void cp_async16(uint32_t dst, const void* src) {
    asm volatile("cp.async.cg.shared.global [%0], [%1], 16;" :: "r"(dst), "l"(src));
}
__device__ __forceinline__ void cp_commit() { asm volatile("cp.async.commit_group;"); }
__device__ __forceinline__ void cp_wait0() { asm volatile("cp.async.wait_group 0;"); }
__device__ __forceinline__ void cp_wait1() { asm volatile("cp.async.wait_group 1;"); }

// ---------------------------------------------------------------------------
// Weight transpose + fp16 convert, 4 weights per launch
// ---------------------------------------------------------------------------
__global__ void wconv4_kernel(const float* __restrict__ W0,
                              const float* __restrict__ W1,
                              const float* __restrict__ W2,
                              const float* __restrict__ W3) {
    __shared__ float t[32][33];
    int z = blockIdx.z;
    const float* W = (z == 0) ? W0 : (z == 1) ? W1 : (z == 2) ? W2 : W3;
    size_t base = (size_t)z * DD * DD;
    int k0 = blockIdx.y * 32, n0 = blockIdx.x * 32;
    t[threadIdx.y][threadIdx.x] = W[(k0 + threadIdx.y) * DD + n0 + threadIdx.x];
    __syncthreads();
    g_wh[base + (size_t)(n0 + threadIdx.y) * DD + k0 + threadIdx.x] =
        __float2half_rn(t[threadIdx.x][threadIdx.y]);
}

// ---------------------------------------------------------------------------
// Activation fp16 convert, 3 inputs per launch
// ---------------------------------------------------------------------------
__global__ void aconv3_kernel(const float4* __restrict__ a0,
                              const float4* __restrict__ a1,
                              const float4* __restrict__ a2) {
    int z = blockIdx.y;
    const float4* in = (z == 0) ? a0 : (z == 1) ? a1 : a2;
    int idx = blockIdx.x * blockDim.x + threadIdx.x;
    float4 a = in[idx];
    ((uint2*)g_ah)[(size_t)z * (GM * GK / 4) + idx] = make_uint2(
        packh2(__float2half_rn(a.x), __float2half_rn(a.y)),
        packh2(__float2half_rn(a.z), __float2half_rn(a.w)));
}

// ---------------------------------------------------------------------------
// RoPE tables
// ---------------------------------------------------------------------------
__global__ void rope_table_kernel() {
    int idx = blockIdx.x * blockDim.x + threadIdx.x;
    int p = idx >> 5, i = idx & 31;
    double inv = exp(-((double)(2 * i) / 64.0) * log(10000.0));
    float angf = (float)((double)p * inv);
    double a = (double)angf;
    double n = rint(a * 0.15915494309189535);
    float r = (float)(a - n * 6.283185307179586);
    g_cos[p * 32 + i] = cosf(r);
    g_sin[p * 32 + i] = sinf(r);
}

// ---------------------------------------------------------------------------
// GEMM fp16: CTA 128x128, warp tile 32x64 (4M x 2N warps), BK=32,
// 2-stage cp.async, 2 CTAs/SM.
// mode 1: fused epilogue (bias + RoPE for z<2) -> fp16 [B,H,S,DK]
// mode 0: f32 epilogue with bias -> C   (A slot 0, W slot 3)
// ---------------------------------------------------------------------------
#define ST_B   10240
#define STAGEH 20480           // (128 A rows + 128 B rows) * 80
#define GEMM_SMEM (2 * STAGEH) // 40960

__global__ void __launch_bounds__(256, 2) gemm_f16_kernel(
    int mode,
    const float* __restrict__ bq, const float* __restrict__ bk,
    const float* __restrict__ bv,
    float* __restrict__ C) {
    extern __shared__ char smem[];
    uint32_t sbase = smem_u32(smem);

    int tid = threadIdx.x;
    int lane = tid & 31, w = tid >> 5;
    int wm = w & 3, wn = w >> 2;         // 4 M-warps x 2 N-warps
    int bm = blockIdx.y * 128, bn = blockIdx.x * 128;
    int z = blockIdx.z;
    int aslot = mode ? z : 0;
    int wslot = mode ? z : 3;

    const __half* Ah = g_ah + (size_t)aslot * GM * GK;
    const __half* Bh = g_wh + (size_t)wslot * DD * DD;

    float acc[2][8][4] = {};

    uint32_t a_row  = wm * 32 + (lane & 15);
    uint32_t a_coff = (lane >> 4) * 16;
    uint32_t b_rl   = wn * 64 + (lane & 7);
    uint32_t b_coff = ((lane >> 3) & 1) * 16;

    auto load_stage = [&](int k0, int stage) {
        uint32_t stb = sbase + stage * STAGEH;
#pragma unroll
        for (int i = 0; i < 4; i++) {
            int idx = tid + i * 256;   // 0..1023
            if (idx < 512) {
                int r = idx >> 2, c = idx & 3;
                cp_async16(stb + r * PITCH + c * 16,
                           Ah + (size_t)(bm + r) * GK + k0 + c * 8);
            } else {
                int j = idx - 512;
                int r = j >> 2, c = j & 3;
                cp_async16(stb + ST_B + r * PITCH + c * 16,
                           Bh + (size_t)(bn + r) * GK + k0 + c * 8);
            }
        }
        cp_commit();
    };

    const int NC = GK / 32;
    load_stage(0, 0);
    int buf = 0;

    for (int c = 0; c < NC; c++) {
        cp_wait0();
        __syncthreads();
        if (c + 1 < NC) load_stage((c + 1) * 32, buf ^ 1);

        uint32_t stb = sbase + buf * STAGEH;
#pragma unroll
        for (int ks = 0; ks < 2; ks++) {
            uint32_t kb = ks * 32;
            uint32_t ah[2][4], bh[8][2];
#pragma unroll
            for (int mi = 0; mi < 2; mi++)
                ldsm_x4(ah[mi], stb + (a_row + mi * 16) * PITCH + kb + a_coff);
#pragma unroll
            for (int ni = 0; ni < 8; ni++)
                ldsm_x2(bh[ni], stb + ST_B + (b_rl + ni * 8) * PITCH + kb + b_coff);
#pragma unroll
            for (int mi = 0; mi < 2; mi++)
#pragma unroll
                for (int ni = 0; ni < 8; ni++)
                    mma_f16(acc[mi][ni], ah[mi], bh[ni]);
        }
        buf ^= 1;
    }

    int r0 = bm + wm * 32 + (lane >> 2);
    int c0 = bn + wn * 64 + (lane & 3) * 2;

    if (mode == 0) {
        const float* bias = bq;   // caller passes bo here
#pragma unroll
        for (int mi = 0; mi < 2; mi++) {
#pragma unroll
            for (int ni = 0; ni < 8; ni++) {
                int row = r0 + mi * 16;
                int col = c0 + ni * 8;
                float bb0 = bias[col], bb1 = bias[col + 1];
                *(float2*)&C[(size_t)row * GN + col] =
                    make_float2(acc[mi][ni][0] + bb0, acc[mi][ni][1] + bb1);
                *(float2*)&C[(size_t)(row + 8) * GN + col] =
                    make_float2(acc[mi][ni][2] + bb0, acc[mi][ni][3] + bb1);
            }
        }
        return;
    }

    // fused epilogue: bias + (RoPE for z<2) -> fp16 [B,H,S,DK]
    const float* bias = (z == 0) ? bq : (z == 1) ? bk : bv;
    __half* outh = (z == 0) ? g_qh2 : (z == 1) ? g_kh2 : g_vh2;
    int hh = (bn >> 6) + wn;

    if (z == 2) {
#pragma unroll
        for (int mi = 0; mi < 2; mi++) {
#pragma unroll
            for (int hf = 0; hf < 2; hf++) {
                int row = r0 + mi * 16 + hf * 8;
                int s = row & (SS - 1), bb = row >> 11;
                size_t base = ((size_t)(bb * HH + hh) * SS + s) * 64;
#pragma unroll
                for (int ni = 0; ni < 8; ni++) {
                    int d = (lane & 3) * 2 + ni * 8;
                    int cn = c0 + ni * 8;
                    *(__half2*)&outh[base + d] = __floats2half2_rn(
                        acc[mi][ni][2 * hf]     + bias[cn],
                        acc[mi][ni][2 * hf + 1] + bias[cn + 1]);
                }
            }
        }
    } else {
#pragma unroll
        for (int mi = 0; mi < 2; mi++) {
#pragma unroll
            for (int hf = 0; hf < 2; hf++) {
                int row = r0 + mi * 16 + hf * 8;
                int s = row & (SS - 1), bb = row >> 11;
                size_t base = ((size_t)(bb * HH + hh) * SS + s) * 64;
#pragma unroll
                for (int ni = 0; ni < 4; ni++) {
                    int d = (lane & 3) * 2 + ni * 8;
                    int cn = c0 + ni * 8;
                    float x0a = acc[mi][ni][2 * hf]       + bias[cn];
                    float x0b = acc[mi][ni][2 * hf + 1]   + bias[cn + 1];
                    float x1a = acc[mi][ni + 4][2 * hf]     + bias[cn + 32];
                    float x1b = acc[mi][ni + 4][2 * hf + 1] + bias[cn + 33];
                    float cA = g_cos[s * 32 + d],  cB = g_cos[s * 32 + d + 1];
                    float sA = g_sin[s * 32 + d],  sB = g_sin[s * 32 + d + 1];
                    *(__half2*)&outh[base + d] = __floats2half2_rn(
                        x0a * cA - x1a * sA, x0b * cB - x1b * sB);
                    *(__half2*)&outh[base + d + 32] = __floats2half2_rn(
                        x1a * cA + x0a * sA, x1b * cB + x0b * sB);
                }
            }
        }
    }
}

// ---------------------------------------------------------------------------
// Flash attention, fp16 mma.sync, 3-stage cp.async KV pipeline (unchanged)
// ---------------------------------------------------------------------------
#define APITCH 144
#define AS_Q   0
#define AS_KV  18432
#define KVSTG  18432
#define ATTN_SMEM (18432 + 3 * KVSTG)   // 73728

__global__ void __launch_bounds__(256) attn_f16_kernel() {
    extern __shared__ char smem[];
    uint32_t sbase = smem_u32(smem);
    int tid = threadIdx.x;
    int lane = tid & 31, w = tid >> 5;
    int qt = blockIdx.x, h = blockIdx.y, b = blockIdx.z;

    size_t hb   = (size_t)(b * HH + h) * SS * DKK;
    size_t qoff = hb + (size_t)qt * 128 * DKK;

    auto load_kv = [&](int j0, int stage) {
        size_t kvb = hb + (size_t)j0 * 64 * DKK;
        uint32_t stb = sbase + AS_KV + stage * KVSTG;
#pragma unroll
        for (int i = 0; i < 4; i++) {
            int idx = tid + i * 256;
            int arr = idx >> 9;
            int s2 = idx & 511;
            int r = s2 >> 3, c = s2 & 7;
            const __half* src = (arr ? g_vh2 : g_kh2) + kvb + r * 64 + c * 8;
            cp_async16(stb + arr * 9216 + r * APITCH + c * 16, src);
        }
        cp_commit();
    };

    {
        const uint4* q4 = (const uint4*)g_qh2 + qoff / 8;
#pragma unroll
        for (int i = 0; i < 4; i++) {
            int idx = tid + i * 256;
            int r = idx >> 3, c = idx & 7;
            *(uint4*)(smem + AS_Q + r * APITCH + c * 16) = q4[r * 8 + c];
        }
    }
    int jmax = 2 * qt + 1;
    load_kv(0, 0);
    load_kv(1, 1);
    __syncthreads();

    uint32_t qf[4][4];
    {
        uint32_t arow = w * 16 + (lane & 15);
        uint32_t acoff = (lane >> 4) * 16;
#pragma unroll
        for (int ks = 0; ks < 4; ks++)
            ldsm_x4(qf[ks], sbase + AS_Q + arow * APITCH + ks * 32 + acoff);
    }

    float o[8][4] = {};
    float m0 = -1e30f, m1 = -1e30f, l0 = 0.0f, l1 = 0.0f;
    int row0 = qt * 128 + w * 16 + (lane >> 2);
    int row1 = row0 + 8;

    for (int j0 = 0; j0 <= jmax; j0++) {
        if (j0 < jmax) cp_wait1(); else cp_wait0();
        __syncthreads();
        if (j0 + 2 <= jmax) load_kv(j0 + 2, (j0 + 2) % 3);

        uint32_t kvb_s = sbase + AS_KV + (j0 % 3) * KVSTG;

        float sacc[8][4] = {};
#pragma unroll
        for (int ks = 0; ks < 4; ks++) {
#pragma unroll
            for (int nt = 0; nt < 8; nt++) {
                uint32_t k2[2];
                ldsm_x2(k2, kvb_s + (nt * 8 + (lane & 7)) * APITCH
                            + ks * 32 + ((lane >> 3) & 1) * 16);
                mma_f16(sacc[nt], qf[ks], k2);
            }
        }

        bool domask = (j0 >= 2 * qt);
        int colb = j0 * 64 + (lane & 3) * 2;
        float mx0 = -1e30f, mx1 = -1e30f;
#pragma unroll
        for (int nt = 0; nt < 8; nt++) {
            float s0 = sacc[nt][0] * 0.125f;
            float s1 = sacc[nt][1] * 0.125f;
            float s2 = sacc[nt][2] * 0.125f;
            float s3 = sacc[nt][3] * 0.125f;
            if (domask) {
                int c0 = colb + nt * 8;
                if (c0     > row0) s0 = -1e30f;
                if (c0 + 1 > row0) s1 = -1e30f;
                if (c0     > row1) s2 = -1e30f;
                if (c0 + 1 > row1) s3 = -1e30f;
            }
            sacc[nt][0] = s0; sacc[nt][1] = s1;
            sacc[nt][2] = s2; sacc[nt][3] = s3;
            mx0 = fmaxf(mx0, fmaxf(s0, s1));
            mx1 = fmaxf(mx1, fmaxf(s2, s3));
        }
        mx0 = fmaxf(mx0, __shfl_xor_sync(0xffffffffu, mx0, 1));
        mx0 = fmaxf(mx0, __shfl_xor_sync(0xffffffffu, mx0, 2));
        mx1 = fmaxf(mx1, __shfl_xor_sync(0xffffffffu, mx1, 1));
        mx1 = fmaxf(mx1, __shfl_xor_sync(0xffffffffu, mx1, 2));

        float mn0 = fmaxf(m0, mx0), mn1 = fmaxf(m1, mx1);
        float al0 = __expf(m0 - mn0), al1 = __expf(m1 - mn1);
        m0 = mn0; m1 = mn1;

        uint32_t pf[8][2];
        float ls0 = 0.0f, ls1 = 0.0f;
#pragma unroll
        for (int nt = 0; nt < 8; nt++) {
            float p0 = __expf(sacc[nt][0] - mn0);
            float p1 = __expf(sacc[nt][1] - mn0);
            float p2 = __expf(sacc[nt][2] - mn1);
            float p3 = __expf(sacc[nt][3] - mn1);
            ls0 += p0 + p1; ls1 += p2 + p3;
            pf[nt][0] = packh2(__float2half_rn(p0), __float2half_rn(p1));
            pf[nt][1] = packh2(__float2half_rn(p2), __float2half_rn(p3));
        }
        l0 = l0 * al0 + ls0;
        l1 = l1 * al1 + ls1;
#pragma unroll
        for (int nt = 0; nt < 8; nt++) {
            o[nt][0] *= al0; o[nt][1] *= al0;
            o[nt][2] *= al1; o[nt][3] *= al1;
        }

#pragma unroll
        for (int ks = 0; ks < 4; ks++) {
            uint32_t pa[4] = {pf[2*ks][0], pf[2*ks][1], pf[2*ks+1][0], pf[2*ks+1][1]};
#pragma unroll
            for (int dn = 0; dn < 8; dn++) {
                uint32_t v2[2];
                ldsm_x2_t(v2, kvb_s + 9216
                    + (ks * 16 + (lane & 7) + ((lane >> 3) & 1) * 8) * APITCH + dn * 16);
                mma_f16(o[dn], pa, v2);
            }
        }
    }

    float lr0 = l0 + __shfl_xor_sync(0xffffffffu, l0, 1);
    lr0 += __shfl_xor_sync(0xffffffffu, lr0, 2);
    float lr1 = l1 + __shfl_xor_sync(0xffffffffu, l1, 1);
    lr1 += __shfl_xor_sync(0xffffffffu, lr1, 2);
    float inv0 = 1.0f / lr0, inv1 = 1.0f / lr1;

    __half* O0 = g_ah + ((size_t)b * SS + row0) * DD + h * 64;
    __half* O1 = g_ah + ((size_t)b * SS + row1) * DD + h * 64;
#pragma unroll
    for (int dn = 0; dn < 8; dn++) {
        int col = dn * 8 + (lane & 3) * 2;
        *(__half2*)&O0[col] = __floats2half2_rn(o[dn][0] * inv0, o[dn][1] * inv0);
        *(__half2*)&O1[col] = __floats2half2_rn(o[dn][2] * inv1, o[dn][3] * inv1);
    }
}

// ---------------------------------------------------------------------------
// Launch
// ---------------------------------------------------------------------------
extern "C" void kernel_launch(void* const* d_in, const int* in_sizes, int n_in,
                              void* d_out, int out_size) {
    const float* q  = (const float*)d_in[0];
    const float* k  = (const float*)d_in[1];
    const float* v  = (const float*)d_in[2];
    const float* Wq = (const float*)d_in[4];
    const float* bq = (const float*)d_in[5];
    const float* Wk = (const float*)d_in[6];
    const float* bk = (const float*)d_in[7];
    const float* Wv = (const float*)d_in[8];
    const float* bv = (const float*)d_in[9];
    const float* Wo = (const float*)d_in[10];
    const float* bo = (const float*)d_in[11];
    float* out = (float*)d_out;

    cudaFuncSetAttribute(gemm_f16_kernel, cudaFuncAttributeMaxDynamicSharedMemorySize, GEMM_SMEM);
    cudaFuncSetAttribute(attn_f16_kernel, cudaFuncAttributeMaxDynamicSharedMemorySize, ATTN_SMEM);

    const int NCONV = (GM * GK / 4) / 256;   // 4096

    aconv3_kernel<<<dim3(NCONV, 3), 256>>>((const float4*)q, (const float4*)k, (const float4*)v);
    wconv4_kernel<<<dim3(32, 32, 4), dim3(32, 32)>>>(Wq, Wk, Wv, Wo);
    rope_table_kernel<<<256, 256>>>();

    // QKV projection, fused bias+RoPE+fp16 epilogue
    gemm_f16_kernel<<<dim3(GN / 128, GM / 128, 3), 256, GEMM_SMEM>>>(
        1, bq, bk, bv, nullptr);

    // attention (writes fp16 to g_ah slot 0)
    attn_f16_kernel<<<dim3(SS / 128, HH, BB), 256, ATTN_SMEM>>>();

    // output projection
    gemm_f16_kernel<<<dim3(GN / 128, GM / 128, 1), 256, GEMM_SMEM>>>(
        0, bo, nullptr, nullptr, out);
}

// round 11
// speedup vs baseline: 7.1113x; 1.0355x over previous
#include <cuda_runtime.h>
#include <cuda_fp16.h>
#include <cstdint>
#include <math.h>

#define BB 2
#define SS 2048
#define DD 1024
#define HH 16
#define DKK 64

#define GM 4096
#define GN 1024
#define GK 1024
#define PITCH 144   // gemm smem row pitch: 64 fp16 + 8 pad

// ---------------------------------------------------------------------------
// Scratch
// ---------------------------------------------------------------------------
__device__ float g_cos[SS*32];
__device__ float g_sin[SS*32];
__device__ __half g_wh[4*DD*DD];   // fp16 weights [N,K]: Wq,Wk,Wv,Wo
__device__ __half g_ah[3*GM*GK];   // fp16 activations; slot0 reused for attn out
__device__ __half g_qh2[BB*SS*DD]; // [B,H,S,DK]
__device__ __half g_kh2[BB*SS*DD];
__device__ __half g_vh2[BB*SS*DD];

// ---------------------------------------------------------------------------
// helpers
// ---------------------------------------------------------------------------
__device__ __forceinline__ uint32_t smem_u32(const void* p) {
    uint32_t a;
    asm("{ .reg .u64 t; cvta.to.shared.u64 t, %1; cvt.u32.u64 %0, t; }"
        : "=r"(a) : "l"(p));
    return a;
}
__device__ __forceinline__ void ldsm_x4(uint32_t* r, uint32_t addr) {
    asm volatile("ldmatrix.sync.aligned.m8n8.x4.shared.b16 {%0,%1,%2,%3}, [%4];"
        : "=r"(r[0]), "=r"(r[1]), "=r"(r[2]), "=r"(r[3]) : "r"(addr));
}
__device__ __forceinline__ void ldsm_x2(uint32_t* r, uint32_t addr) {
    asm volatile("ldmatrix.sync.aligned.m8n8.x2.shared.b16 {%0,%1}, [%2];"
        : "=r"(r[0]), "=r"(r[1]) : "r"(addr));
}
__device__ __forceinline__ void ldsm_x2_t(uint32_t* r, uint32_t addr) {
    asm volatile("ldmatrix.sync.aligned.m8n8.x2.trans.shared.b16 {%0,%1}, [%2];"
        : "=r"(r[0]), "=r"(r[1]) : "r"(addr));
}
__device__ __forceinline__ void mma_f16(float* d, const uint32_t* a, const uint32_t* b) {
    asm volatile(
        "mma.sync.aligned.m16n8k16.row.col.f32.f16.f16.f32 "
        "{%0,%1,%2,%3}, {%4,%5,%6,%7}, {%8,%9}, {%0,%1,%2,%3};"
        : "+f"(d[0]), "+f"(d[1]), "+f"(d[2]), "+f"(d[3])
        : "r"(a[0]), "r"(a[1]), "r"(a[2]), "r"(a[3]), "r"(b[0]), "r"(b[1]));
}
__device__ __forceinline__ uint32_t packh2(__half lo, __half hi) {
    return ((uint32_t)__half_as_ushort(hi) << 16) | __half_as_ushort(lo);
}
__device__ __forceinline__ void cp_async16(uint32_t dst, const void* src) {
    asm volatile("cp.async.cg.shared.global [%0], [%1], 16;" :: "r"(dst), "l"(src));
}
__device__ __forceinline__ void cp_commit() { asm volatile("cp.async.commit_group;"); }
__device__ __forceinline__ void cp_wait0() { asm volatile("cp.async.wait_group 0;"); }
__device__ __forceinline__ void cp_wait1() { asm volatile("cp.async.wait_group 1;"); }

// ---------------------------------------------------------------------------
// Weight transpose + fp16 convert, 4 weights per launch
// ---------------------------------------------------------------------------
__global__ void wconv4_kernel(const float* __restrict__ W0,
                              const float* __restrict__ W1,
                              const float* __restrict__ W2,
                              const float* __restrict__ W3) {
    __shared__ float t[32][33];
    int z = blockIdx.z;
    const float* W = (z == 0) ? W0 : (z == 1) ? W1 : (z == 2) ? W2 : W3;
    size_t base = (size_t)z * DD * DD;
    int k0 = blockIdx.y * 32, n0 = blockIdx.x * 32;
    t[threadIdx.y][threadIdx.x] = W[(k0 + threadIdx.y) * DD + n0 + threadIdx.x];
    __syncthreads();
    g_wh[base + (size_t)(n0 + threadIdx.y) * DD + k0 + threadIdx.x] =
        __float2half_rn(t[threadIdx.x][threadIdx.y]);
}

// ---------------------------------------------------------------------------
// Activation fp16 convert, 3 inputs per launch
// ---------------------------------------------------------------------------
__global__ void aconv3_kernel(const float4* __restrict__ a0,
                              const float4* __restrict__ a1,
                              const float4* __restrict__ a2) {
    int z = blockIdx.y;
    const float4* in = (z == 0) ? a0 : (z == 1) ? a1 : a2;
    int idx = blockIdx.x * blockDim.x + threadIdx.x;
    float4 a = in[idx];
    ((uint2*)g_ah)[(size_t)z * (GM * GK / 4) + idx] = make_uint2(
        packh2(__float2half_rn(a.x), __float2half_rn(a.y)),
        packh2(__float2half_rn(a.z), __float2half_rn(a.w)));
}

// ---------------------------------------------------------------------------
// RoPE tables
// ---------------------------------------------------------------------------
__global__ void rope_table_kernel() {
    int idx = blockIdx.x * blockDim.x + threadIdx.x;
    int p = idx >> 5, i = idx & 31;
    double inv = exp(-((double)(2 * i) / 64.0) * log(10000.0));
    float angf = (float)((double)p * inv);
    double a = (double)angf;
    double n = rint(a * 0.15915494309189535);
    float r = (float)(a - n * 6.283185307179586);
    g_cos[p * 32 + i] = cosf(r);
    g_sin[p * 32 + i] = sinf(r);
}

// ---------------------------------------------------------------------------
// GEMM fp16: CTA 128x128, warp tile 32x64 (4M x 2N warps), BK=64,
// 2-stage cp.async, 2 CTAs/SM.
// mode 1: fused epilogue (bias + RoPE for z<2) -> fp16 [B,H,S,DK]
// mode 0: f32 epilogue with bias -> C   (A slot 0, W slot 3)
// ---------------------------------------------------------------------------
#define ST_B   18432           // 128 rows * 144
#define STAGEH 36864
#define GEMM_SMEM (2 * STAGEH) // 73728

__global__ void __launch_bounds__(256, 2) gemm_f16_kernel(
    int mode,
    const float* __restrict__ bq, const float* __restrict__ bk,
    const float* __restrict__ bv,
    float* __restrict__ C) {
    extern __shared__ char smem[];
    uint32_t sbase = smem_u32(smem);

    int tid = threadIdx.x;
    int lane = tid & 31, w = tid >> 5;
    int wm = w & 3, wn = w >> 2;         // 4 M-warps x 2 N-warps
    int bm = blockIdx.y * 128, bn = blockIdx.x * 128;
    int z = blockIdx.z;
    int aslot = mode ? z : 0;
    int wslot = mode ? z : 3;

    const __half* Ah = g_ah + (size_t)aslot * GM * GK;
    const __half* Bh = g_wh + (size_t)wslot * DD * DD;

    float acc[2][8][4] = {};

    uint32_t a_row  = wm * 32 + (lane & 15);
    uint32_t a_coff = (lane >> 4) * 16;
    uint32_t b_rl   = wn * 64 + (lane & 7);
    uint32_t b_coff = ((lane >> 3) & 1) * 16;

    auto load_stage = [&](int k0, int stage) {
        uint32_t stb = sbase + stage * STAGEH;
#pragma unroll
        for (int i = 0; i < 8; i++) {
            int idx = tid + i * 256;   // 0..2047
            if (idx < 1024) {          // A: 128 rows x 8 chunks (64 cols)
                int r = idx >> 3, c = idx & 7;
                cp_async16(stb + r * PITCH + c * 16,
                           Ah + (size_t)(bm + r) * GK + k0 + c * 8);
            } else {                   // B: 128 rows x 8 chunks
                int j = idx - 1024;
                int r = j >> 3, c = j & 7;
                cp_async16(stb + ST_B + r * PITCH + c * 16,
                           Bh + (size_t)(bn + r) * GK + k0 + c * 8);
            }
        }
        cp_commit();
    };

    const int NC = GK / 64;
    load_stage(0, 0);
    int buf = 0;

    for (int c = 0; c < NC; c++) {
        cp_wait0();
        __syncthreads();
        if (c + 1 < NC) load_stage((c + 1) * 64, buf ^ 1);

        uint32_t stb = sbase + buf * STAGEH;
#pragma unroll
        for (int ks = 0; ks < 4; ks++) {
            uint32_t kb = ks * 32;     // 16 cols * 2B per k-step
            uint32_t ah[2][4], bh[8][2];
#pragma unroll
            for (int mi = 0; mi < 2; mi++)
                ldsm_x4(ah[mi], stb + (a_row + mi * 16) * PITCH + kb + a_coff);
#pragma unroll
            for (int ni = 0; ni < 8; ni++)
                ldsm_x2(bh[ni], stb + ST_B + (b_rl + ni * 8) * PITCH + kb + b_coff);
#pragma unroll
            for (int mi = 0; mi < 2; mi++)
#pragma unroll
                for (int ni = 0; ni < 8; ni++)
                    mma_f16(acc[mi][ni], ah[mi], bh[ni]);
        }
        buf ^= 1;
    }

    int r0 = bm + wm * 32 + (lane >> 2);
    int c0 = bn + wn * 64 + (lane & 3) * 2;

    if (mode == 0) {
        const float* bias = bq;   // caller passes bo here
#pragma unroll
        for (int mi = 0; mi < 2; mi++) {
#pragma unroll
            for (int ni = 0; ni < 8; ni++) {
                int row = r0 + mi * 16;
                int col = c0 + ni * 8;
                float bb0 = bias[col], bb1 = bias[col + 1];
                *(float2*)&C[(size_t)row * GN + col] =
                    make_float2(acc[mi][ni][0] + bb0, acc[mi][ni][1] + bb1);
                *(float2*)&C[(size_t)(row + 8) * GN + col] =
                    make_float2(acc[mi][ni][2] + bb0, acc[mi][ni][3] + bb1);
            }
        }
        return;
    }

    // fused epilogue: bias + (RoPE for z<2) -> fp16 [B,H,S,DK]
    const float* bias = (z == 0) ? bq : (z == 1) ? bk : bv;
    __half* outh = (z == 0) ? g_qh2 : (z == 1) ? g_kh2 : g_vh2;
    int hh = (bn >> 6) + wn;

    if (z == 2) {
#pragma unroll
        for (int mi = 0; mi < 2; mi++) {
#pragma unroll
            for (int hf = 0; hf < 2; hf++) {
                int row = r0 + mi * 16 + hf * 8;
                int s = row & (SS - 1), bb = row >> 11;
                size_t base = ((size_t)(bb * HH + hh) * SS + s) * 64;
#pragma unroll
                for (int ni = 0; ni < 8; ni++) {
                    int d = (lane & 3) * 2 + ni * 8;
                    int cn = c0 + ni * 8;
                    *(__half2*)&outh[base + d] = __floats2half2_rn(
                        acc[mi][ni][2 * hf]     + bias[cn],
                        acc[mi][ni][2 * hf + 1] + bias[cn + 1]);
                }
            }
        }
    } else {
#pragma unroll
        for (int mi = 0; mi < 2; mi++) {
#pragma unroll
            for (int hf = 0; hf < 2; hf++) {
                int row = r0 + mi * 16 + hf * 8;
                int s = row & (SS - 1), bb = row >> 11;
                size_t base = ((size_t)(bb * HH + hh) * SS + s) * 64;
#pragma unroll
                for (int ni = 0; ni < 4; ni++) {
                    int d = (lane & 3) * 2 + ni * 8;
                    int cn = c0 + ni * 8;
                    float x0a = acc[mi][ni][2 * hf]       + bias[cn];
                    float x0b = acc[mi][ni][2 * hf + 1]   + bias[cn + 1];
                    float x1a = acc[mi][ni + 4][2 * hf]     + bias[cn + 32];
                    float x1b = acc[mi][ni + 4][2 * hf + 1] + bias[cn + 33];
                    float cA = g_cos[s * 32 + d],  cB = g_cos[s * 32 + d + 1];
                    float sA = g_sin[s * 32 + d],  sB = g_sin[s * 32 + d + 1];
                    *(__half2*)&outh[base + d] = __floats2half2_rn(
                        x0a * cA - x1a * sA, x0b * cB - x1b * sB);
                    *(__half2*)&outh[base + d + 32] = __floats2half2_rn(
                        x1a * cA + x0a * sA, x1b * cB + x0b * sB);
                }
            }
        }
    }
}

// ---------------------------------------------------------------------------
// Flash attention, fp16 mma.sync, 3-stage cp.async KV pipeline, 2 CTAs/SM
// ---------------------------------------------------------------------------
#define APITCH 144
#define AS_Q   0
#define AS_KV  18432
#define KVSTG  18432
#define ATTN_SMEM (18432 + 3 * KVSTG)   // 73728

__global__ void __launch_bounds__(256, 2) attn_f16_kernel() {
    extern __shared__ char smem[];
    uint32_t sbase = smem_u32(smem);
    int tid = threadIdx.x;
    int lane = tid & 31, w = tid >> 5;
    int qt = blockIdx.x, h = blockIdx.y, b = blockIdx.z;

    size_t hb   = (size_t)(b * HH + h) * SS * DKK;
    size_t qoff = hb + (size_t)qt * 128 * DKK;

    auto load_kv = [&](int j0, int stage) {
        size_t kvb = hb + (size_t)j0 * 64 * DKK;
        uint32_t stb = sbase + AS_KV + stage * KVSTG;
#pragma unroll
        for (int i = 0; i < 4; i++) {
            int idx = tid + i * 256;
            int arr = idx >> 9;
            int s2 = idx & 511;
            int r = s2 >> 3, c = s2 & 7;
            const __half* src = (arr ? g_vh2 : g_kh2) + kvb + r * 64 + c * 8;
            cp_async16(stb + arr * 9216 + r * APITCH + c * 16, src);
        }
        cp_commit();
    };

    {
        const uint4* q4 = (const uint4*)g_qh2 + qoff / 8;
#pragma unroll
        for (int i = 0; i < 4; i++) {
            int idx = tid + i * 256;
            int r = idx >> 3, c = idx & 7;
            *(uint4*)(smem + AS_Q + r * APITCH + c * 16) = q4[r * 8 + c];
        }
    }
    int jmax = 2 * qt + 1;
    load_kv(0, 0);
    load_kv(1, 1);
    __syncthreads();

    uint32_t qf[4][4];
    {
        uint32_t arow = w * 16 + (lane & 15);
        uint32_t acoff = (lane >> 4) * 16;
#pragma unroll
        for (int ks = 0; ks < 4; ks++)
            ldsm_x4(qf[ks], sbase + AS_Q + arow * APITCH + ks * 32 + acoff);
    }

    float o[8][4] = {};
    float m0 = -1e30f, m1 = -1e30f, l0 = 0.0f, l1 = 0.0f;
    int row0 = qt * 128 + w * 16 + (lane >> 2);
    int row1 = row0 + 8;

    for (int j0 = 0; j0 <= jmax; j0++) {
        if (j0 < jmax) cp_wait1(); else cp_wait0();
        __syncthreads();
        if (j0 + 2 <= jmax) load_kv(j0 + 2, (j0 + 2) % 3);

        uint32_t kvb_s = sbase + AS_KV + (j0 % 3) * KVSTG;

        float sacc[8][4] = {};
#pragma unroll
        for (int ks = 0; ks < 4; ks++) {
#pragma unroll
            for (int nt = 0; nt < 8; nt++) {
                uint32_t k2[2];
                ldsm_x2(k2, kvb_s + (nt * 8 + (lane & 7)) * APITCH
                            + ks * 32 + ((lane >> 3) & 1) * 16);
                mma_f16(sacc[nt], qf[ks], k2);
            }
        }

        bool domask = (j0 >= 2 * qt);
        int colb = j0 * 64 + (lane & 3) * 2;
        float mx0 = -1e30f, mx1 = -1e30f;
#pragma unroll
        for (int nt = 0; nt < 8; nt++) {
            float s0 = sacc[nt][0] * 0.125f;
            float s1 = sacc[nt][1] * 0.125f;
            float s2 = sacc[nt][2] * 0.125f;
            float s3 = sacc[nt][3] * 0.125f;
            if (domask) {
                int c0 = colb + nt * 8;
                if (c0     > row0) s0 = -1e30f;
                if (c0 + 1 > row0) s1 = -1e30f;
                if (c0     > row1) s2 = -1e30f;
                if (c0 + 1 > row1) s3 = -1e30f;
            }
            sacc[nt][0] = s0; sacc[nt][1] = s1;
            sacc[nt][2] = s2; sacc[nt][3] = s3;
            mx0 = fmaxf(mx0, fmaxf(s0, s1));
            mx1 = fmaxf(mx1, fmaxf(s2, s3));
        }
        mx0 = fmaxf(mx0, __shfl_xor_sync(0xffffffffu, mx0, 1));
        mx0 = fmaxf(mx0, __shfl_xor_sync(0xffffffffu, mx0, 2));
        mx1 = fmaxf(mx1, __shfl_xor_sync(0xffffffffu, mx1, 1));
        mx1 = fmaxf(mx1, __shfl_xor_sync(0xffffffffu, mx1, 2));

        float mn0 = fmaxf(m0, mx0), mn1 = fmaxf(m1, mx1);
        float al0 = __expf(m0 - mn0), al1 = __expf(m1 - mn1);
        m0 = mn0; m1 = mn1;

        uint32_t pf[8][2];
        float ls0 = 0.0f, ls1 = 0.0f;
#pragma unroll
        for (int nt = 0; nt < 8; nt++) {
            float p0 = __expf(sacc[nt][0] - mn0);
            float p1 = __expf(sacc[nt][1] - mn0);
            float p2 = __expf(sacc[nt][2] - mn1);
            float p3 = __expf(sacc[nt][3] - mn1);
            ls0 += p0 + p1; ls1 += p2 + p3;
            pf[nt][0] = packh2(__float2half_rn(p0), __float2half_rn(p1));
            pf[nt][1] = packh2(__float2half_rn(p2), __float2half_rn(p3));
        }
        l0 = l0 * al0 + ls0;
        l1 = l1 * al1 + ls1;
#pragma unroll
        for (int nt = 0; nt < 8; nt++) {
            o[nt][0] *= al0; o[nt][1] *= al0;
            o[nt][2] *= al1; o[nt][3] *= al1;
        }

#pragma unroll
        for (int ks = 0; ks < 4; ks++) {
            uint32_t pa[4] = {pf[2*ks][0], pf[2*ks][1], pf[2*ks+1][0], pf[2*ks+1][1]};
#pragma unroll
            for (int dn = 0; dn < 8; dn++) {
                uint32_t v2[2];
                ldsm_x2_t(v2, kvb_s + 9216
                    + (ks * 16 + (lane & 7) + ((lane >> 3) & 1) * 8) * APITCH + dn * 16);
                mma_f16(o[dn], pa, v2);
            }
        }
    }

    float lr0 = l0 + __shfl_xor_sync(0xffffffffu, l0, 1);
    lr0 += __shfl_xor_sync(0xffffffffu, lr0, 2);
    float lr1 = l1 + __shfl_xor_sync(0xffffffffu, l1, 1);
    lr1 += __shfl_xor_sync(0xffffffffu, lr1, 2);
    float inv0 = 1.0f / lr0, inv1 = 1.0f / lr1;

    __half* O0 = g_ah + ((size_t)b * SS + row0) * DD + h * 64;
    __half* O1 = g_ah + ((size_t)b * SS + row1) * DD + h * 64;
#pragma unroll
    for (int dn = 0; dn < 8; dn++) {
        int col = dn * 8 + (lane & 3) * 2;
        *(__half2*)&O0[col] = __floats2half2_rn(o[dn][0] * inv0, o[dn][1] * inv0);
        *(__half2*)&O1[col] = __floats2half2_rn(o[dn][2] * inv1, o[dn][3] * inv1);
    }
}

// ---------------------------------------------------------------------------
// Launch
// ---------------------------------------------------------------------------
extern "C" void kernel_launch(void* const* d_in, const int* in_sizes, int n_in,
                              void* d_out, int out_size) {
    const float* q  = (const float*)d_in[0];
    const float* k  = (const float*)d_in[1];
    const float* v  = (const float*)d_in[2];
    const float* Wq = (const float*)d_in[4];
    const float* bq = (const float*)d_in[5];
    const float* Wk = (const float*)d_in[6];
    const float* bk = (const float*)d_in[7];
    const float* Wv = (const float*)d_in[8];
    const float* bv = (const float*)d_in[9];
    const float* Wo = (const float*)d_in[10];
    const float* bo = (const float*)d_in[11];
    float* out = (float*)d_out;

    cudaFuncSetAttribute(gemm_f16_kernel, cudaFuncAttributeMaxDynamicSharedMemorySize, GEMM_SMEM);
    cudaFuncSetAttribute(attn_f16_kernel, cudaFuncAttributeMaxDynamicSharedMemorySize, ATTN_SMEM);

    const int NCONV = (GM * GK / 4) / 256;   // 4096

    aconv3_kernel<<<dim3(NCONV, 3), 256>>>((const float4*)q, (const float4*)k, (const float4*)v);
    wconv4_kernel<<<dim3(32, 32, 4), dim3(32, 32)>>>(Wq, Wk, Wv, Wo);
    rope_table_kernel<<<256, 256>>>();

    // QKV projection, fused bias+RoPE+fp16 epilogue
    gemm_f16_kernel<<<dim3(GN / 128, GM / 128, 3), 256, GEMM_SMEM>>>(
        1, bq, bk, bv, nullptr);

    // attention (writes fp16 to g_ah slot 0)
    attn_f16_kernel<<<dim3(SS / 128, HH, BB), 256, ATTN_SMEM>>>();

    // output projection
    gemm_f16_kernel<<<dim3(GN / 128, GM / 128, 1), 256, GEMM_SMEM>>>(
        0, bo, nullptr, nullptr, out);
}